// round 11
// baseline (speedup 1.0000x reference)
#include <cuda_runtime.h>
#include <cuda_bf16.h>
#include <stdint.h>

#define DEV __device__ __forceinline__
typedef unsigned long long ull;

#define B_ 1024
#define U_ 512
#define SIGD 16512

// ---------- scratch ----------
__device__ float d_mu[B_];
__device__ float d_rstd[B_];
__device__ float d_skip[B_ * 3];
__device__ float d_sigw[B_ * 3];
__device__ __align__(16) float d_z[B_ * 1536];
__device__ __align__(16) float d_aggin[3 * B_ * 128];
__device__ __align__(16) float d_subE[3 * B_ * 1152];
__device__ __align__(16) float d_subW[3 * 1152 * 128];
__device__ __align__(16) float d_agg[B_ * 384];
__device__ __align__(16) float d_part[4 * B_ * U_];

// ---------- helpers ----------
DEV float sigm(float x) { return 1.f / (1.f + __expf(-x)); }
DEV uint32_t f2tf(float f) {
    uint32_t r;
    asm("cvt.rna.tf32.f32 %0,%1;" : "=r"(r) : "f"(f));
    return r;
}
DEV void mma_tf32(float acc[4], const uint32_t a[4], const uint32_t b[2]) {
    asm volatile(
        "mma.sync.aligned.m16n8k8.row.col.f32.tf32.tf32.f32 "
        "{%0,%1,%2,%3},{%4,%5,%6,%7},{%8,%9},{%0,%1,%2,%3};"
        : "+f"(acc[0]), "+f"(acc[1]), "+f"(acc[2]), "+f"(acc[3])
        : "r"(a[0]), "r"(a[1]), "r"(a[2]), "r"(a[3]), "r"(b[0]), "r"(b[1]));
}

DEV void kan_expand(float xn, float e[9]) {
    e[0] = xn * sigm(xn);
#pragma unroll
    for (int j = 1; j < 9; j++) e[j] = 0.f;
    float tp = (xn + 2.2f) * 2.5f;
    float tf = floorf(tp);
    if (tf >= 0.f && tf <= 10.f) {
        int t = (int)tf;
        float u = tp - tf, u2 = u * u, u3 = u2 * u, omu = 1.f - u;
        float v0 = omu * omu * omu * (1.f / 6.f);
        float v1 = (3.f * u3 - 6.f * u2 + 4.f) * (1.f / 6.f);
        float v2 = (-3.f * u3 + 3.f * u2 + 3.f * u + 1.f) * (1.f / 6.f);
        float v3 = u3 * (1.f / 6.f);
        if (t >= 3)           e[t - 2] = v0;
        if (t >= 2 && t <= 9) e[t - 1] = v1;
        if (t >= 1 && t <= 8) e[t]     = v2;
        if (t <= 7)           e[t + 1] = v3;
    }
}

DEV float red128(float v, float* sh) {
    int t = threadIdx.x;
    sh[t] = v; __syncthreads();
#pragma unroll
    for (int s = 64; s > 0; s >>= 1) { if (t < s) sh[t] += sh[t + s]; __syncthreads(); }
    float r = sh[0]; __syncthreads();
    return r;
}

// ---------- K1: sig LN stats (closed form) + skip ----------
__global__ __launch_bounds__(128) void k_stats(const float* __restrict__ x,
                                               const float* __restrict__ skw,
                                               const float* __restrict__ skb) {
    __shared__ float xs[128], sh[128];
    int b = blockIdx.x, t = threadIdx.x;
    float xv = x[b * 128 + t];
    xs[t] = xv; __syncthreads();
    float S = red128(xv, sh);
    float Q = red128(xv * xv, sh);
    if (t == 0) {
        float mean = (S + 0.5f * S * S) / (float)SIGD;
        float m2 = (Q + 0.25f * Q * Q) / (float)SIGD;
        d_mu[b] = mean;
        d_rstd[b] = rsqrtf(m2 - mean * mean + 1e-3f);
    }
    float a0 = 0.f, a1 = 0.f, a2 = 0.f;
    for (int i = t; i < SIGD; i += 128) {
        float sv = (i < 128) ? xs[i] : 0.5f * xs[(i - 128) >> 7] * xs[(i - 128) & 127];
        a0 += sv * skw[i * 3 + 0];
        a1 += sv * skw[i * 3 + 1];
        a2 += sv * skw[i * 3 + 2];
    }
    a0 = red128(a0, sh); a1 = red128(a1, sh); a2 = red128(a2, sh);
    if (t == 0) {
        d_skip[b * 3 + 0] = a0 + skb[0];
        d_skip[b * 3 + 1] = a1 + skb[1];
        d_skip[b * 3 + 2] = a2 + skb[2];
    }
}

// ---------- K2: big KAN GEMM, tf32 mma, double-buffered single-sync pipeline ----------
#define LDA4 76
#define LDB4 136
#define ABUF (128 * LDA4)          // 9728 words
#define BBUF (72 * LDB4)           // 9792 words
#define BUFW (ABUF + BBUF)         // 19520 words (mult of 32 -> bank-invariant)
#define SM_MMA (2 * BUFW * 4)      // 156160 bytes
__global__ __launch_bounds__(256, 1) void k_mma(const float* __restrict__ x,
                                                const float* __restrict__ lng,
                                                const float* __restrict__ lnb,
                                                const float* __restrict__ wb,
                                                const float* __restrict__ ws) {
    extern __shared__ uint32_t sm4[];
    int tid = threadIdx.x, lane = tid & 31, wid = tid >> 5;
    int ks = blockIdx.x, mg = blockIdx.y, ng = blockIdx.z;
    int rowBase = mg * 128, colBase = ng * 128;
    int warpRow = (wid & 3) * 32, warpCol = (wid >> 2) * 64;
    int g = lane >> 2, tg = lane & 3;
    int rsel = tid >> 5, n4 = (tid & 31) * 4;

    // hoisted per-thread expand constants (4 tasks: 8 feats x 128 rows / 256 thr)
    int rowp[4], flp[4];
    float mup[4], rsp[4];
    const float* xrp[4];
#pragma unroll
    for (int p = 0; p < 4; p++) {
        int task = tid + p * 256;
        rowp[p] = task >> 3;
        flp[p] = task & 7;
        mup[p] = d_mu[rowBase + rowp[p]];
        rsp[p] = d_rstd[rowBase + rowp[p]];
        xrp[p] = x + (size_t)(rowBase + rowp[p]) * 128;
    }

    float acc[2][8][4];
#pragma unroll
    for (int mi = 0; mi < 2; mi++)
#pragma unroll
        for (int ni = 0; ni < 8; ni++)
#pragma unroll
            for (int q = 0; q < 4; q++) acc[mi][ni][q] = 0.f;

    // ---- prologue: produce chunk 0 into buf 0 ----
    {
        int f0 = ks * 4128;
#pragma unroll
        for (int p = 0; p < 4; p++) {
            int fg = f0 + flp[p];
            float val;
            if (fg < 128) val = __ldg(xrp[p] + fg);
            else {
                int q = fg - 128;
                val = 0.5f * __ldg(xrp[p] + (q >> 7)) * __ldg(xrp[p] + (q & 127));
            }
            float xn = (val - mup[p]) * rsp[p] * __ldg(lng + fg) + __ldg(lnb + fg);
            float e[9];
            kan_expand(xn, e);
            int off = rowp[p] * LDA4 + flp[p] * 9;
#pragma unroll
            for (int j = 0; j < 9; j++) sm4[off + j] = f2tf(e[j]);
        }
#pragma unroll
        for (int i = 0; i < 9; i++) {
            int kl = i * 8 + rsel;
            int kg = f0 * 9 + kl;
            int f = kg / 9, jj = kg - f * 9;
            const float* p = (jj == 0) ? wb + (size_t)f * 512
                                       : ws + ((size_t)f * 8 + (jj - 1)) * 512;
            float4 v = *(const float4*)(p + colBase + n4);
            uint4 w;
            w.x = f2tf(v.x); w.y = f2tf(v.y); w.z = f2tf(v.z); w.w = f2tf(v.w);
            *(uint4*)&sm4[ABUF + kl * LDB4 + n4] = w;
        }
    }
    __syncthreads();

    // ---- main loop: MMA(buf) interleaved with produce(buf^1), one barrier ----
    for (int ch = 0; ch < 516; ch++) {
        int buf = ch & 1;
        uint32_t* Ac = sm4 + buf * BUFW;
        uint32_t* Bc = Ac + ABUF;
        uint32_t* An = sm4 + (buf ^ 1) * BUFW;
        uint32_t* Bn = An + ABUF;
        bool more = (ch < 515);
        int f0n = ks * 4128 + (ch + 1) * 8;

        // prefetch next chunk's B into regs (latency hidden under MMAs)
        float4 vB[9];
        if (more) {
#pragma unroll
            for (int i = 0; i < 9; i++) {
                int kl = i * 8 + rsel;
                int kg = f0n * 9 + kl;
                int f = kg / 9, jj = kg - f * 9;
                const float* p = (jj == 0) ? wb + (size_t)f * 512
                                           : ws + ((size_t)f * 8 + (jj - 1)) * 512;
                vB[i] = *(const float4*)(p + colBase + n4);
            }
        }

#pragma unroll
        for (int i = 0; i < 9; i++) {
            int k0 = i * 8;
            // --- MMA kstep i on current buffer ---
            uint32_t aF[2][4];
#pragma unroll
            for (int mi = 0; mi < 2; mi++) {
                int r = warpRow + mi * 16;
                aF[mi][0] = Ac[(r + g) * LDA4 + k0 + tg];
                aF[mi][1] = Ac[(r + 8 + g) * LDA4 + k0 + tg];
                aF[mi][2] = Ac[(r + g) * LDA4 + k0 + tg + 4];
                aF[mi][3] = Ac[(r + 8 + g) * LDA4 + k0 + tg + 4];
            }
            uint32_t bF[8][2];
#pragma unroll
            for (int ni = 0; ni < 8; ni++) {
                int c = warpCol + ni * 8 + g;
                bF[ni][0] = Bc[(k0 + tg) * LDB4 + c];
                bF[ni][1] = Bc[(k0 + tg + 4) * LDB4 + c];
            }
#pragma unroll
            for (int mi = 0; mi < 2; mi++)
#pragma unroll
                for (int ni = 0; ni < 8; ni++)
                    mma_tf32(acc[mi][ni], aF[mi], bF[ni]);

            // --- produce slice i for next chunk into other buffer ---
            if (more) {
                if (i < 4) {
                    int p = i;
                    int fg = f0n + flp[p];
                    float val;
                    if (fg < 128) val = __ldg(xrp[p] + fg);
                    else {
                        int q = fg - 128;
                        val = 0.5f * __ldg(xrp[p] + (q >> 7)) * __ldg(xrp[p] + (q & 127));
                    }
                    float xn = (val - mup[p]) * rsp[p] * __ldg(lng + fg) + __ldg(lnb + fg);
                    float e[9];
                    kan_expand(xn, e);
                    int off = rowp[p] * LDA4 + flp[p] * 9;
#pragma unroll
                    for (int j = 0; j < 9; j++) An[off + j] = f2tf(e[j]);
                }
                {
                    int kl = i * 8 + rsel;
                    uint4 w;
                    w.x = f2tf(vB[i].x); w.y = f2tf(vB[i].y);
                    w.z = f2tf(vB[i].z); w.w = f2tf(vB[i].w);
                    *(uint4*)&Bn[kl * LDB4 + n4] = w;
                }
            }
        }
        __syncthreads();
    }

    // ---- epilogue: write K-split partials ----
    float* dp = d_part + (size_t)ks * (B_ * U_);
#pragma unroll
    for (int mi = 0; mi < 2; mi++)
#pragma unroll
        for (int ni = 0; ni < 8; ni++) {
            int row = rowBase + warpRow + mi * 16 + g;
            int col = colBase + warpCol + ni * 8 + tg * 2;
            *(float2*)&dp[(size_t)row * 512 + col] = make_float2(acc[mi][ni][0], acc[mi][ni][1]);
            *(float2*)&dp[(size_t)(row + 8) * 512 + col] = make_float2(acc[mi][ni][2], acc[mi][ni][3]);
        }
}

// ---------- K3: head (folds the K-split reduce) ----------
__global__ __launch_bounds__(128) void k_head(const float* __restrict__ g2g,
                                              const float* __restrict__ g2b,
                                              const float* __restrict__ k2base,
                                              const float* __restrict__ k2spl,
                                              const float* __restrict__ gw, const float* __restrict__ gb,
                                              const float* __restrict__ sw, const float* __restrict__ sb,
                                              const float* __restrict__ lg, const float* __restrict__ lb) {
    __shared__ float sh[128];
    int b = blockIdx.x, t = threadIdx.x;
    float v[4], S = 0.f, Q = 0.f;
#pragma unroll
    for (int m = 0; m < 4; m++) {
        float s = 0.f;
#pragma unroll
        for (int ks = 0; ks < 4; ks++)
            s += d_part[(size_t)ks * (B_ * U_) + b * 512 + t + 128 * m];
        v[m] = s;
        S += s; Q += s * s;
    }
    S = red128(S, sh); Q = red128(Q, sh);
    float mean = S / 512.f;
    float rstd = rsqrtf(Q / 512.f - mean * mean + 1e-3f);
    float a0 = 0.f, a1 = 0.f, a2 = 0.f;
#pragma unroll
    for (int m = 0; m < 4; m++) {
        int i = t + 128 * m;
        float xn = (v[m] - mean) * rstd * g2g[i] + g2b[i];
        float e[9];
        kan_expand(xn, e);
        a0 += e[0] * k2base[i * 3 + 0];
        a1 += e[0] * k2base[i * 3 + 1];
        a2 += e[0] * k2base[i * 3 + 2];
#pragma unroll
        for (int j = 0; j < 8; j++) {
            const float* sp = k2spl + (size_t)(i * 8 + j) * 3;
            a0 += e[1 + j] * sp[0];
            a1 += e[1 + j] * sp[1];
            a2 += e[1 + j] * sp[2];
        }
    }
    a0 = red128(a0, sh); a1 = red128(a1, sh); a2 = red128(a2, sh);
    if (t == 0) {
        float h2[3] = {a0, a1, a2};
        float y[3];
#pragma unroll
        for (int o = 0; o < 3; o++) {
            float g1 = gb[o], s1 = sb[o];
#pragma unroll
            for (int p = 0; p < 3; p++) { g1 += h2[p] * gw[p * 3 + o]; s1 += h2[p] * sw[p * 3 + o]; }
            y[o] = d_skip[b * 3 + o] + g1 * sigm(s1);
        }
        float m = (y[0] + y[1] + y[2]) * (1.f / 3.f);
        float var = ((y[0] - m) * (y[0] - m) + (y[1] - m) * (y[1] - m) + (y[2] - m) * (y[2] - m)) * (1.f / 3.f);
        float rs = rsqrtf(var + 1e-3f);
        float yn[3], mx = -1e30f;
#pragma unroll
        for (int o = 0; o < 3; o++) { yn[o] = (y[o] - m) * rs * lg[o] + lb[o]; mx = fmaxf(mx, yn[o]); }
        float e0 = __expf(yn[0] - mx), e1 = __expf(yn[1] - mx), e2 = __expf(yn[2] - mx);
        float inv = 1.f / (e0 + e1 + e2);
        d_sigw[b * 3 + 0] = e0 * inv;
        d_sigw[b * 3 + 1] = e1 * inv;
        d_sigw[b * 3 + 2] = e2 * inv;
    }
}

// ---------- K4: LSTM gates via tf32 MMA ----------
#define LDAZ 36
#define LDBZ 136
__global__ __launch_bounds__(256) void k_z(const float* __restrict__ x, const float* __restrict__ h0,
                                           const float* __restrict__ W1, const float* __restrict__ W2,
                                           const float* __restrict__ bias) {
    __shared__ uint32_t As4[128 * LDAZ];
    __shared__ uint32_t Bs4[32 * LDBZ];
    int tid = threadIdx.x, lane = tid & 31, wid = tid >> 5;
    int colBase = blockIdx.x * 128, rowBase = blockIdx.y * 128;
    int warpRow = (wid & 3) * 32, warpCol = (wid >> 2) * 64;
    int g = lane >> 2, tg = lane & 3;
    int rsel = tid >> 5, n4 = (tid & 31) * 4;
    int arow = tid >> 1, ahalf = tid & 1;

    float acc[2][8][4];
#pragma unroll
    for (int mi = 0; mi < 2; mi++)
#pragma unroll
        for (int ni = 0; ni < 8; ni++)
#pragma unroll
            for (int q = 0; q < 4; q++) acc[mi][ni][q] = 0.f;

    for (int kt = 0; kt < 640; kt += 32) {
        const float* src = (kt < 128) ? x + (size_t)(rowBase + arow) * 128 + kt + ahalf * 16
                                      : h0 + (size_t)(rowBase + arow) * 512 + (kt - 128) + ahalf * 16;
#pragma unroll
        for (int q = 0; q < 4; q++) {
            float4 v = *(const float4*)(src + q * 4);
            uint4 w;
            w.x = f2tf(v.x); w.y = f2tf(v.y); w.z = f2tf(v.z); w.w = f2tf(v.w);
            *(uint4*)&As4[arow * LDAZ + ahalf * 16 + q * 4] = w;
        }
#pragma unroll
        for (int i = 0; i < 4; i++) {
            int kl = i * 8 + rsel;
            int kg = kt + kl;
            const float* p = (kg < 128) ? W1 + (size_t)kg * 1536 + colBase + n4
                                        : W2 + (size_t)(kg - 128) * 1536 + colBase + n4;
            float4 v = *(const float4*)p;
            uint4 w;
            w.x = f2tf(v.x); w.y = f2tf(v.y); w.z = f2tf(v.z); w.w = f2tf(v.w);
            *(uint4*)&Bs4[kl * LDBZ + n4] = w;
        }
        __syncthreads();
#pragma unroll
        for (int ks2 = 0; ks2 < 4; ks2++) {
            int k0 = ks2 * 8;
            uint32_t aF[2][4];
#pragma unroll
            for (int mi = 0; mi < 2; mi++) {
                int r = warpRow + mi * 16;
                aF[mi][0] = As4[(r + g) * LDAZ + k0 + tg];
                aF[mi][1] = As4[(r + 8 + g) * LDAZ + k0 + tg];
                aF[mi][2] = As4[(r + g) * LDAZ + k0 + tg + 4];
                aF[mi][3] = As4[(r + 8 + g) * LDAZ + k0 + tg + 4];
            }
            uint32_t bF[8][2];
#pragma unroll
            for (int ni = 0; ni < 8; ni++) {
                int c = warpCol + ni * 8 + g;
                bF[ni][0] = Bs4[(k0 + tg) * LDBZ + c];
                bF[ni][1] = Bs4[(k0 + tg + 4) * LDBZ + c];
            }
#pragma unroll
            for (int mi = 0; mi < 2; mi++)
#pragma unroll
                for (int ni = 0; ni < 8; ni++)
                    mma_tf32(acc[mi][ni], aF[mi], bF[ni]);
        }
        __syncthreads();
    }
#pragma unroll
    for (int mi = 0; mi < 2; mi++)
#pragma unroll
        for (int ni = 0; ni < 8; ni++) {
            int row = rowBase + warpRow + mi * 16 + g;
            int col = colBase + warpCol + ni * 8 + tg * 2;
            d_z[(size_t)row * 1536 + col]     = sigm(acc[mi][ni][0] + bias[col]);
            d_z[(size_t)row * 1536 + col + 1] = sigm(acc[mi][ni][1] + bias[col + 1]);
            d_z[(size_t)(row + 8) * 1536 + col]     = sigm(acc[mi][ni][2] + bias[col]);
            d_z[(size_t)(row + 8) * 1536 + col + 1] = sigm(acc[mi][ni][3] + bias[col + 1]);
        }
}

// ---------- K5: agg_in ----------
__global__ __launch_bounds__(256) void k_aggin(const float* __restrict__ x, const float* __restrict__ ss,
                                               const float* __restrict__ rki, const float* __restrict__ rks) {
    __shared__ float As[16 * 64], Bs[16 * 64];
    int tid = threadIdx.x, n = blockIdx.z;
    int rowBase = blockIdx.y * 64, colBase = blockIdx.x * 64;
    int r0 = (tid >> 4) * 4, c0 = (tid & 15) * 4;
    float acc[4][4] = {};
    for (int kt = 0; kt < 256; kt += 16) {
        for (int idx = tid; idx < 1024; idx += 256) {
            int kk = idx & 15, m = idx >> 4, kg = kt + kk, b = rowBase + m;
            As[kk * 64 + m] = (kg < 128) ? x[b * 128 + kg] : ss[n * 131072 + b * 128 + kg - 128];
            int cc = idx & 63, k2 = idx >> 6, kg2 = kt + k2, c = colBase + cc;
            Bs[k2 * 64 + cc] = (kg2 < 128) ? rki[n * 16384 + kg2 * 128 + c]
                                           : rks[n * 16384 + (kg2 - 128) * 128 + c];
        }
        __syncthreads();
#pragma unroll
        for (int k = 0; k < 16; k++) {
            float4 a = *(const float4*)&As[k * 64 + r0];
            float4 bb = *(const float4*)&Bs[k * 64 + c0];
            float av[4] = {a.x, a.y, a.z, a.w}, bv[4] = {bb.x, bb.y, bb.z, bb.w};
#pragma unroll
            for (int i = 0; i < 4; i++)
#pragma unroll
                for (int j = 0; j < 4; j++) acc[i][j] += av[i] * bv[j];
        }
        __syncthreads();
    }
#pragma unroll
    for (int i = 0; i < 4; i++)
#pragma unroll
        for (int j = 0; j < 4; j++)
            d_aggin[n * 131072 + (rowBase + r0 + i) * 128 + colBase + c0 + j] = acc[i][j];
}

// ---------- K6: sub LN + expansion ----------
__global__ __launch_bounds__(128) void k_subexpand(const float* __restrict__ lg,
                                                   const float* __restrict__ lb) {
    __shared__ float sh[128];
    int bx = blockIdx.x, t = threadIdx.x;
    int n = bx >> 10;
    float v = d_aggin[bx * 128 + t];
    float S = red128(v, sh), Q = red128(v * v, sh);
    float mean = S * (1.f / 128.f);
    float rstd = rsqrtf(Q * (1.f / 128.f) - mean * mean + 1e-3f);
    float xn = (v - mean) * rstd * lg[n * 128 + t] + lb[n * 128 + t];
    float e[9];
    kan_expand(xn, e);
    size_t base = (size_t)bx * 1152 + t * 9;
#pragma unroll
    for (int j = 0; j < 9; j++) d_subE[base + j] = e[j];
}

// ---------- K7: pack sub weights ----------
__global__ void k_packW(const float* __restrict__ bw, const float* __restrict__ sw) {
    int idx = blockIdx.x * 256 + threadIdx.x;
    if (idx >= 3 * 1152 * 128) return;
    int n = idx / 147456, rem = idx - n * 147456;
    int k = rem >> 7, o = rem & 127;
    int f = k / 9, j = k - f * 9;
    d_subW[idx] = (j == 0) ? bw[n * 16384 + f * 128 + o]
                           : sw[n * 131072 + (f * 8 + j - 1) * 128 + o];
}

// ---------- K8: sub GEMM + epilogue ----------
__global__ __launch_bounds__(256) void k_subgemm(const float* __restrict__ ss,
                                                 const float* __restrict__ subk,
                                                 float* __restrict__ out_ss) {
    __shared__ float As[16 * 64], Bs[16 * 64];
    int tid = threadIdx.x, n = blockIdx.z;
    int rowBase = blockIdx.y * 64, colBase = blockIdx.x * 64;
    int r0 = (tid >> 4) * 4, c0 = (tid & 15) * 4;
    float acc[4][4] = {};
    for (int kt = 0; kt < 1152; kt += 16) {
        for (int idx = tid; idx < 1024; idx += 256) {
            int kk = idx & 15, m = idx >> 4, b = rowBase + m;
            As[kk * 64 + m] = d_subE[((size_t)(n * 1024 + b)) * 1152 + kt + kk];
            int cc = idx & 63, k2 = idx >> 6, c = colBase + cc;
            Bs[k2 * 64 + cc] = d_subW[n * 147456 + (kt + k2) * 128 + c];
        }
        __syncthreads();
#pragma unroll
        for (int k = 0; k < 16; k++) {
            float4 a = *(const float4*)&As[k * 64 + r0];
            float4 bb = *(const float4*)&Bs[k * 64 + c0];
            float av[4] = {a.x, a.y, a.z, a.w}, bv[4] = {bb.x, bb.y, bb.z, bb.w};
#pragma unroll
            for (int i = 0; i < 4; i++)
#pragma unroll
                for (int j = 0; j < 4; j++) acc[i][j] += av[i] * bv[j];
        }
        __syncthreads();
    }
#pragma unroll
    for (int i = 0; i < 4; i++)
#pragma unroll
        for (int j = 0; j < 4; j++) {
            int b = rowBase + r0 + i, o = colBase + c0 + j;
            float v = acc[i][j] * d_sigw[b * 3 + n];
            d_agg[b * 384 + n * 128 + o] = v;
            out_ss[n * 131072 + b * 128 + o] =
                subk[n * 256 + o] * v + ss[n * 131072 + b * 128 + o] * subk[n * 256 + 128 + o];
        }
}

// ---------- K9: x_o GEMM + final c, h ----------
__global__ __launch_bounds__(256) void k_final(const float* __restrict__ aw, const float* __restrict__ ab,
                                               const float* __restrict__ c0p, float* __restrict__ out) {
    __shared__ float As[16 * 64], Bs[16 * 64];
    int tid = threadIdx.x;
    int rowBase = blockIdx.y * 64, colBase = blockIdx.x * 64;
    int r0 = (tid >> 4) * 4, cc0 = (tid & 15) * 4;
    float acc[4][4] = {};
    for (int kt = 0; kt < 384; kt += 16) {
        for (int idx = tid; idx < 1024; idx += 256) {
            int kk = idx & 15, m = idx >> 4;
            As[kk * 64 + m] = d_agg[(rowBase + m) * 384 + kt + kk];
            int cc = idx & 63, k2 = idx >> 6;
            Bs[k2 * 64 + cc] = aw[(kt + k2) * 512 + colBase + cc];
        }
        __syncthreads();
#pragma unroll
        for (int k = 0; k < 16; k++) {
            float4 a = *(const float4*)&As[k * 64 + r0];
            float4 bb = *(const float4*)&Bs[k * 64 + cc0];
            float av[4] = {a.x, a.y, a.z, a.w}, bv[4] = {bb.x, bb.y, bb.z, bb.w};
#pragma unroll
            for (int i = 0; i < 4; i++)
#pragma unroll
                for (int j = 0; j < 4; j++) acc[i][j] += av[i] * bv[j];
        }
        __syncthreads();
    }
#pragma unroll
    for (int i = 0; i < 4; i++)
#pragma unroll
        for (int j = 0; j < 4; j++) {
            int b = rowBase + r0 + i, c = colBase + cc0 + j;
            float xo = sigm(acc[i][j] + ab[c]);
            float zi = d_z[b * 1536 + c];
            float zf = d_z[b * 1536 + 512 + c];
            float zc = d_z[b * 1536 + 1024 + c];
            float cv = zf * c0p[b * 512 + c] + zi * zc;
            out[b * 512 + c] = xo * tanhf(cv);
            out[B_ * U_ + b * 512 + c] = cv;
        }
}

// ---------- launch ----------
extern "C" void kernel_launch(void* const* d_in, const int* in_sizes, int n_in,
                              void* d_out, int out_size) {
    const float* inputs   = (const float*)d_in[0];
    const float* h0       = (const float*)d_in[1];
    const float* c0       = (const float*)d_in[2];
    const float* sub_st   = (const float*)d_in[3];
    const float* kern     = (const float*)d_in[4];
    const float* rkern    = (const float*)d_in[5];
    const float* bias     = (const float*)d_in[6];
    const float* sub_k    = (const float*)d_in[7];
    const float* sub_rki  = (const float*)d_in[8];
    const float* sub_rks  = (const float*)d_in[9];
    const float* agg_w    = (const float*)d_in[10];
    const float* agg_b    = (const float*)d_in[11];
    const float* sub_lng  = (const float*)d_in[12];
    const float* sub_lnb  = (const float*)d_in[13];
    const float* sub_bw   = (const float*)d_in[14];
    const float* sub_sw   = (const float*)d_in[15];
    const float* g_skw    = (const float*)d_in[16];
    const float* g_skb    = (const float*)d_in[17];
    const float* k1_lng   = (const float*)d_in[18];
    const float* k1_lnb   = (const float*)d_in[19];
    const float* k1_base  = (const float*)d_in[20];
    const float* k1_spl   = (const float*)d_in[21];
    const float* k2_lng   = (const float*)d_in[22];
    const float* k2_lnb   = (const float*)d_in[23];
    const float* k2_base  = (const float*)d_in[24];
    const float* k2_spl   = (const float*)d_in[25];
    const float* gw       = (const float*)d_in[26];
    const float* gb       = (const float*)d_in[27];
    const float* sw       = (const float*)d_in[28];
    const float* sb       = (const float*)d_in[29];
    const float* lg       = (const float*)d_in[30];
    const float* lb       = (const float*)d_in[31];
    float* out = (float*)d_out;

    static bool attr_set = false;
    if (!attr_set) {
        cudaFuncSetAttribute(k_mma, cudaFuncAttributeMaxDynamicSharedMemorySize, SM_MMA);
        attr_set = true;
    }

    k_stats<<<B_, 128>>>(inputs, g_skw, g_skb);
    k_mma<<<dim3(4, 8, 4), 256, SM_MMA>>>(inputs, k1_lng, k1_lnb, k1_base, k1_spl);
    k_head<<<B_, 128>>>(k2_lng, k2_lnb, k2_base, k2_spl, gw, gb, sw, sb, lg, lb);
    k_z<<<dim3(12, 8), 256>>>(inputs, h0, kern, rkern, bias);
    k_aggin<<<dim3(2, 16, 3), 256>>>(inputs, sub_st, sub_rki, sub_rks);
    k_subexpand<<<3 * B_, 128>>>(sub_lng, sub_lnb);
    k_packW<<<(3 * 1152 * 128 + 255) / 256, 256>>>(sub_bw, sub_sw);
    k_subgemm<<<dim3(2, 16, 3), 256>>>(sub_st, sub_k, out + 2 * B_ * U_);
    k_final<<<dim3(8, 16), 256>>>(agg_w, agg_b, c0, out);
}

// round 12
// speedup vs baseline: 1.3552x; 1.3552x over previous
#include <cuda_runtime.h>
#include <cuda_bf16.h>
#include <stdint.h>

#define DEV __device__ __forceinline__
typedef unsigned long long ull;

#define B_ 1024
#define U_ 512
#define SIGD 16512

// ---------- scratch ----------
__device__ float d_mu[B_];
__device__ float d_rstd[B_];
__device__ float d_skip[B_ * 3];
__device__ float d_sigw[B_ * 3];
__device__ __align__(16) float d_z[B_ * 1536];
__device__ __align__(16) float d_aggin[3 * B_ * 128];
__device__ __align__(16) float d_subE[3 * B_ * 1152];
__device__ __align__(16) float d_subW[3 * 1152 * 128];
__device__ __align__(16) float d_agg[B_ * 384];
__device__ __align__(16) float d_part[8 * B_ * U_];

// ---------- helpers ----------
DEV float sigm(float x) { return 1.f / (1.f + __expf(-x)); }
DEV uint32_t f2tf(float f) {
    uint32_t r;
    asm("cvt.rna.tf32.f32 %0,%1;" : "=r"(r) : "f"(f));
    return r;
}
DEV void mma_tf32(float acc[4], const uint32_t a[4], const uint32_t b[2]) {
    asm volatile(
        "mma.sync.aligned.m16n8k8.row.col.f32.tf32.tf32.f32 "
        "{%0,%1,%2,%3},{%4,%5,%6,%7},{%8,%9},{%0,%1,%2,%3};"
        : "+f"(acc[0]), "+f"(acc[1]), "+f"(acc[2]), "+f"(acc[3])
        : "r"(a[0]), "r"(a[1]), "r"(a[2]), "r"(a[3]), "r"(b[0]), "r"(b[1]));
}

DEV void kan_expand(float xn, float e[9]) {
    e[0] = xn * sigm(xn);
#pragma unroll
    for (int j = 1; j < 9; j++) e[j] = 0.f;
    float tp = (xn + 2.2f) * 2.5f;
    float tf = floorf(tp);
    if (tf >= 0.f && tf <= 10.f) {
        int t = (int)tf;
        float u = tp - tf, u2 = u * u, u3 = u2 * u, omu = 1.f - u;
        float v0 = omu * omu * omu * (1.f / 6.f);
        float v1 = (3.f * u3 - 6.f * u2 + 4.f) * (1.f / 6.f);
        float v2 = (-3.f * u3 + 3.f * u2 + 3.f * u + 1.f) * (1.f / 6.f);
        float v3 = u3 * (1.f / 6.f);
        if (t >= 3)           e[t - 2] = v0;
        if (t >= 2 && t <= 9) e[t - 1] = v1;
        if (t >= 1 && t <= 8) e[t]     = v2;
        if (t <= 7)           e[t + 1] = v3;
    }
}

DEV float red128(float v, float* sh) {
    int t = threadIdx.x;
    sh[t] = v; __syncthreads();
#pragma unroll
    for (int s = 64; s > 0; s >>= 1) { if (t < s) sh[t] += sh[t + s]; __syncthreads(); }
    float r = sh[0]; __syncthreads();
    return r;
}

// ---------- K1: sig LN stats (closed form) + skip ----------
__global__ __launch_bounds__(128) void k_stats(const float* __restrict__ x,
                                               const float* __restrict__ skw,
                                               const float* __restrict__ skb) {
    __shared__ float xs[128], sh[128];
    int b = blockIdx.x, t = threadIdx.x;
    float xv = x[b * 128 + t];
    xs[t] = xv; __syncthreads();
    float S = red128(xv, sh);
    float Q = red128(xv * xv, sh);
    if (t == 0) {
        float mean = (S + 0.5f * S * S) / (float)SIGD;
        float m2 = (Q + 0.25f * Q * Q) / (float)SIGD;
        d_mu[b] = mean;
        d_rstd[b] = rsqrtf(m2 - mean * mean + 1e-3f);
    }
    float a0 = 0.f, a1 = 0.f, a2 = 0.f;
    for (int i = t; i < SIGD; i += 128) {
        float sv = (i < 128) ? xs[i] : 0.5f * xs[(i - 128) >> 7] * xs[(i - 128) & 127];
        a0 += sv * skw[i * 3 + 0];
        a1 += sv * skw[i * 3 + 1];
        a2 += sv * skw[i * 3 + 2];
    }
    a0 = red128(a0, sh); a1 = red128(a1, sh); a2 = red128(a2, sh);
    if (t == 0) {
        d_skip[b * 3 + 0] = a0 + skb[0];
        d_skip[b * 3 + 1] = a1 + skb[1];
        d_skip[b * 3 + 2] = a2 + skb[2];
    }
}

// ---------- K2: big KAN GEMM via mma.sync tf32, 2 CTAs/SM (R8-proven shape) ----------
#define LDA4 76
#define LDB4 136
#define SM_MMA (128 * LDA4 * 4 + 72 * LDB4 * 4)   // 78080
__global__ __launch_bounds__(256, 2) void k_mma(const float* __restrict__ x,
                                                const float* __restrict__ lng,
                                                const float* __restrict__ lnb,
                                                const float* __restrict__ wb,
                                                const float* __restrict__ ws) {
    extern __shared__ uint32_t sm4[];
    uint32_t* As4 = sm4;                 // [row][k] tf32, pad 76
    uint32_t* Bs4 = sm4 + 128 * LDA4;    // [k][n]  tf32, pad 136

    int tid = threadIdx.x, lane = tid & 31, wid = tid >> 5;
    int ks = blockIdx.x, mg = blockIdx.y, ng = blockIdx.z;
    int rowBase = mg * 128, colBase = ng * 128;
    int warpRow = (wid & 3) * 32, warpCol = (wid >> 2) * 64;
    int g = lane >> 2, tg = lane & 3;
    int rsel = tid >> 5, n4 = (tid & 31) * 4;

    float acc[2][8][4];
#pragma unroll
    for (int mi = 0; mi < 2; mi++)
#pragma unroll
        for (int ni = 0; ni < 8; ni++)
#pragma unroll
            for (int q = 0; q < 4; q++) acc[mi][ni][q] = 0.f;

    for (int ch = 0; ch < 258; ch++) {
        int f0 = ks * 2064 + ch * 8;
        // --- A: expand 8 feats x 128 rows into tf32 smem ---
#pragma unroll
        for (int p = 0; p < 4; p++) {
            int task = tid + p * 256;
            int fl = task & 7, row = task >> 3;
            int fg = f0 + fl;
            const float* xr = x + (size_t)(rowBase + row) * 128;
            float val;
            if (fg < 128) val = __ldg(xr + fg);
            else {
                int q = fg - 128;
                val = 0.5f * __ldg(xr + (q >> 7)) * __ldg(xr + (q & 127));
            }
            float xn = (val - d_mu[rowBase + row]) * d_rstd[rowBase + row]
                     * __ldg(lng + fg) + __ldg(lnb + fg);
            float e[9];
            kan_expand(xn, e);
            int off = row * LDA4 + fl * 9;
#pragma unroll
            for (int j = 0; j < 9; j++) As4[off + j] = f2tf(e[j]);
        }
        // --- B: load 72 x 128 fp32, cvt tf32, store [k][n] ---
#pragma unroll
        for (int i = 0; i < 9; i++) {
            int kl = i * 8 + rsel;
            int kg = f0 * 9 + kl;
            int f = kg / 9, jj = kg - f * 9;
            const float* p = (jj == 0) ? wb + (size_t)f * 512
                                       : ws + ((size_t)f * 8 + (jj - 1)) * 512;
            float4 v = *(const float4*)(p + colBase + n4);
            uint4 w;
            w.x = f2tf(v.x); w.y = f2tf(v.y); w.z = f2tf(v.z); w.w = f2tf(v.w);
            *(uint4*)&Bs4[kl * LDB4 + n4] = w;
        }
        __syncthreads();
        // --- MMA: 9 k-steps of 8 ---
#pragma unroll 3
        for (int ks2 = 0; ks2 < 9; ks2++) {
            int k0 = ks2 * 8;
            uint32_t aF[2][4];
#pragma unroll
            for (int mi = 0; mi < 2; mi++) {
                int r = warpRow + mi * 16;
                aF[mi][0] = As4[(r + g) * LDA4 + k0 + tg];
                aF[mi][1] = As4[(r + 8 + g) * LDA4 + k0 + tg];
                aF[mi][2] = As4[(r + g) * LDA4 + k0 + tg + 4];
                aF[mi][3] = As4[(r + 8 + g) * LDA4 + k0 + tg + 4];
            }
            uint32_t bF[8][2];
#pragma unroll
            for (int ni = 0; ni < 8; ni++) {
                int c = warpCol + ni * 8 + g;
                bF[ni][0] = Bs4[(k0 + tg) * LDB4 + c];
                bF[ni][1] = Bs4[(k0 + tg + 4) * LDB4 + c];
            }
#pragma unroll
            for (int mi = 0; mi < 2; mi++)
#pragma unroll
                for (int ni = 0; ni < 8; ni++)
                    mma_tf32(acc[mi][ni], aF[mi], bF[ni]);
        }
        __syncthreads();
    }
    // --- epilogue: write K-split partials ---
    float* dp = d_part + (size_t)ks * (B_ * U_);
#pragma unroll
    for (int mi = 0; mi < 2; mi++)
#pragma unroll
        for (int ni = 0; ni < 8; ni++) {
            int row = rowBase + warpRow + mi * 16 + g;
            int col = colBase + warpCol + ni * 8 + tg * 2;
            *(float2*)&dp[(size_t)row * 512 + col] = make_float2(acc[mi][ni][0], acc[mi][ni][1]);
            *(float2*)&dp[(size_t)(row + 8) * 512 + col] = make_float2(acc[mi][ni][2], acc[mi][ni][3]);
        }
}

// ---------- K3: head (folds the 8-way K-split reduce) ----------
__global__ __launch_bounds__(128) void k_head(const float* __restrict__ g2g,
                                              const float* __restrict__ g2b,
                                              const float* __restrict__ k2base,
                                              const float* __restrict__ k2spl,
                                              const float* __restrict__ gw, const float* __restrict__ gb,
                                              const float* __restrict__ sw, const float* __restrict__ sb,
                                              const float* __restrict__ lg, const float* __restrict__ lb) {
    __shared__ float sh[128];
    int b = blockIdx.x, t = threadIdx.x;
    float v[4], S = 0.f, Q = 0.f;
#pragma unroll
    for (int m = 0; m < 4; m++) {
        float s = 0.f;
#pragma unroll
        for (int ks = 0; ks < 8; ks++)
            s += d_part[(size_t)ks * (B_ * U_) + b * 512 + t + 128 * m];
        v[m] = s;
        S += s; Q += s * s;
    }
    S = red128(S, sh); Q = red128(Q, sh);
    float mean = S / 512.f;
    float rstd = rsqrtf(Q / 512.f - mean * mean + 1e-3f);
    float a0 = 0.f, a1 = 0.f, a2 = 0.f;
#pragma unroll
    for (int m = 0; m < 4; m++) {
        int i = t + 128 * m;
        float xn = (v[m] - mean) * rstd * g2g[i] + g2b[i];
        float e[9];
        kan_expand(xn, e);
        a0 += e[0] * k2base[i * 3 + 0];
        a1 += e[0] * k2base[i * 3 + 1];
        a2 += e[0] * k2base[i * 3 + 2];
#pragma unroll
        for (int j = 0; j < 8; j++) {
            const float* sp = k2spl + (size_t)(i * 8 + j) * 3;
            a0 += e[1 + j] * sp[0];
            a1 += e[1 + j] * sp[1];
            a2 += e[1 + j] * sp[2];
        }
    }
    a0 = red128(a0, sh); a1 = red128(a1, sh); a2 = red128(a2, sh);
    if (t == 0) {
        float h2[3] = {a0, a1, a2};
        float y[3];
#pragma unroll
        for (int o = 0; o < 3; o++) {
            float g1 = gb[o], s1 = sb[o];
#pragma unroll
            for (int p = 0; p < 3; p++) { g1 += h2[p] * gw[p * 3 + o]; s1 += h2[p] * sw[p * 3 + o]; }
            y[o] = d_skip[b * 3 + o] + g1 * sigm(s1);
        }
        float m = (y[0] + y[1] + y[2]) * (1.f / 3.f);
        float var = ((y[0] - m) * (y[0] - m) + (y[1] - m) * (y[1] - m) + (y[2] - m) * (y[2] - m)) * (1.f / 3.f);
        float rs = rsqrtf(var + 1e-3f);
        float yn[3], mx = -1e30f;
#pragma unroll
        for (int o = 0; o < 3; o++) { yn[o] = (y[o] - m) * rs * lg[o] + lb[o]; mx = fmaxf(mx, yn[o]); }
        float e0 = __expf(yn[0] - mx), e1 = __expf(yn[1] - mx), e2 = __expf(yn[2] - mx);
        float inv = 1.f / (e0 + e1 + e2);
        d_sigw[b * 3 + 0] = e0 * inv;
        d_sigw[b * 3 + 1] = e1 * inv;
        d_sigw[b * 3 + 2] = e2 * inv;
    }
}

// ---------- K4: LSTM gates via tf32 MMA ----------
#define LDAZ 36
#define LDBZ 136
__global__ __launch_bounds__(256) void k_z(const float* __restrict__ x, const float* __restrict__ h0,
                                           const float* __restrict__ W1, const float* __restrict__ W2,
                                           const float* __restrict__ bias) {
    __shared__ uint32_t As4[128 * LDAZ];
    __shared__ uint32_t Bs4[32 * LDBZ];
    int tid = threadIdx.x, lane = tid & 31, wid = tid >> 5;
    int colBase = blockIdx.x * 128, rowBase = blockIdx.y * 128;
    int warpRow = (wid & 3) * 32, warpCol = (wid >> 2) * 64;
    int g = lane >> 2, tg = lane & 3;
    int rsel = tid >> 5, n4 = (tid & 31) * 4;
    int arow = tid >> 1, ahalf = tid & 1;

    float acc[2][8][4];
#pragma unroll
    for (int mi = 0; mi < 2; mi++)
#pragma unroll
        for (int ni = 0; ni < 8; ni++)
#pragma unroll
            for (int q = 0; q < 4; q++) acc[mi][ni][q] = 0.f;

    for (int kt = 0; kt < 640; kt += 32) {
        const float* src = (kt < 128) ? x + (size_t)(rowBase + arow) * 128 + kt + ahalf * 16
                                      : h0 + (size_t)(rowBase + arow) * 512 + (kt - 128) + ahalf * 16;
#pragma unroll
        for (int q = 0; q < 4; q++) {
            float4 v = *(const float4*)(src + q * 4);
            uint4 w;
            w.x = f2tf(v.x); w.y = f2tf(v.y); w.z = f2tf(v.z); w.w = f2tf(v.w);
            *(uint4*)&As4[arow * LDAZ + ahalf * 16 + q * 4] = w;
        }
#pragma unroll
        for (int i = 0; i < 4; i++) {
            int kl = i * 8 + rsel;
            int kg = kt + kl;
            const float* p = (kg < 128) ? W1 + (size_t)kg * 1536 + colBase + n4
                                        : W2 + (size_t)(kg - 128) * 1536 + colBase + n4;
            float4 v = *(const float4*)p;
            uint4 w;
            w.x = f2tf(v.x); w.y = f2tf(v.y); w.z = f2tf(v.z); w.w = f2tf(v.w);
            *(uint4*)&Bs4[kl * LDBZ + n4] = w;
        }
        __syncthreads();
#pragma unroll
        for (int ks2 = 0; ks2 < 4; ks2++) {
            int k0 = ks2 * 8;
            uint32_t aF[2][4];
#pragma unroll
            for (int mi = 0; mi < 2; mi++) {
                int r = warpRow + mi * 16;
                aF[mi][0] = As4[(r + g) * LDAZ + k0 + tg];
                aF[mi][1] = As4[(r + 8 + g) * LDAZ + k0 + tg];
                aF[mi][2] = As4[(r + g) * LDAZ + k0 + tg + 4];
                aF[mi][3] = As4[(r + 8 + g) * LDAZ + k0 + tg + 4];
            }
            uint32_t bF[8][2];
#pragma unroll
            for (int ni = 0; ni < 8; ni++) {
                int c = warpCol + ni * 8 + g;
                bF[ni][0] = Bs4[(k0 + tg) * LDBZ + c];
                bF[ni][1] = Bs4[(k0 + tg + 4) * LDBZ + c];
            }
#pragma unroll
            for (int mi = 0; mi < 2; mi++)
#pragma unroll
                for (int ni = 0; ni < 8; ni++)
                    mma_tf32(acc[mi][ni], aF[mi], bF[ni]);
        }
        __syncthreads();
    }
#pragma unroll
    for (int mi = 0; mi < 2; mi++)
#pragma unroll
        for (int ni = 0; ni < 8; ni++) {
            int row = rowBase + warpRow + mi * 16 + g;
            int col = colBase + warpCol + ni * 8 + tg * 2;
            d_z[(size_t)row * 1536 + col]     = sigm(acc[mi][ni][0] + bias[col]);
            d_z[(size_t)row * 1536 + col + 1] = sigm(acc[mi][ni][1] + bias[col + 1]);
            d_z[(size_t)(row + 8) * 1536 + col]     = sigm(acc[mi][ni][2] + bias[col]);
            d_z[(size_t)(row + 8) * 1536 + col + 1] = sigm(acc[mi][ni][3] + bias[col + 1]);
        }
}

// ---------- K5: agg_in ----------
__global__ __launch_bounds__(256) void k_aggin(const float* __restrict__ x, const float* __restrict__ ss,
                                               const float* __restrict__ rki, const float* __restrict__ rks) {
    __shared__ float As[16 * 64], Bs[16 * 64];
    int tid = threadIdx.x, n = blockIdx.z;
    int rowBase = blockIdx.y * 64, colBase = blockIdx.x * 64;
    int r0 = (tid >> 4) * 4, c0 = (tid & 15) * 4;
    float acc[4][4] = {};
    for (int kt = 0; kt < 256; kt += 16) {
        for (int idx = tid; idx < 1024; idx += 256) {
            int kk = idx & 15, m = idx >> 4, kg = kt + kk, b = rowBase + m;
            As[kk * 64 + m] = (kg < 128) ? x[b * 128 + kg] : ss[n * 131072 + b * 128 + kg - 128];
            int cc = idx & 63, k2 = idx >> 6, kg2 = kt + k2, c = colBase + cc;
            Bs[k2 * 64 + cc] = (kg2 < 128) ? rki[n * 16384 + kg2 * 128 + c]
                                           : rks[n * 16384 + (kg2 - 128) * 128 + c];
        }
        __syncthreads();
#pragma unroll
        for (int k = 0; k < 16; k++) {
            float4 a = *(const float4*)&As[k * 64 + r0];
            float4 bb = *(const float4*)&Bs[k * 64 + c0];
            float av[4] = {a.x, a.y, a.z, a.w}, bv[4] = {bb.x, bb.y, bb.z, bb.w};
#pragma unroll
            for (int i = 0; i < 4; i++)
#pragma unroll
                for (int j = 0; j < 4; j++) acc[i][j] += av[i] * bv[j];
        }
        __syncthreads();
    }
#pragma unroll
    for (int i = 0; i < 4; i++)
#pragma unroll
        for (int j = 0; j < 4; j++)
            d_aggin[n * 131072 + (rowBase + r0 + i) * 128 + colBase + c0 + j] = acc[i][j];
}

// ---------- K6: sub LN + expansion ----------
__global__ __launch_bounds__(128) void k_subexpand(const float* __restrict__ lg,
                                                   const float* __restrict__ lb) {
    __shared__ float sh[128];
    int bx = blockIdx.x, t = threadIdx.x;
    int n = bx >> 10;
    float v = d_aggin[bx * 128 + t];
    float S = red128(v, sh), Q = red128(v * v, sh);
    float mean = S * (1.f / 128.f);
    float rstd = rsqrtf(Q * (1.f / 128.f) - mean * mean + 1e-3f);
    float xn = (v - mean) * rstd * lg[n * 128 + t] + lb[n * 128 + t];
    float e[9];
    kan_expand(xn, e);
    size_t base = (size_t)bx * 1152 + t * 9;
#pragma unroll
    for (int j = 0; j < 9; j++) d_subE[base + j] = e[j];
}

// ---------- K7: pack sub weights ----------
__global__ void k_packW(const float* __restrict__ bw, const float* __restrict__ sw) {
    int idx = blockIdx.x * 256 + threadIdx.x;
    if (idx >= 3 * 1152 * 128) return;
    int n = idx / 147456, rem = idx - n * 147456;
    int k = rem >> 7, o = rem & 127;
    int f = k / 9, j = k - f * 9;
    d_subW[idx] = (j == 0) ? bw[n * 16384 + f * 128 + o]
                           : sw[n * 131072 + (f * 8 + j - 1) * 128 + o];
}

// ---------- K8: sub GEMM + epilogue ----------
__global__ __launch_bounds__(256) void k_subgemm(const float* __restrict__ ss,
                                                 const float* __restrict__ subk,
                                                 float* __restrict__ out_ss) {
    __shared__ float As[16 * 64], Bs[16 * 64];
    int tid = threadIdx.x, n = blockIdx.z;
    int rowBase = blockIdx.y * 64, colBase = blockIdx.x * 64;
    int r0 = (tid >> 4) * 4, c0 = (tid & 15) * 4;
    float acc[4][4] = {};
    for (int kt = 0; kt < 1152; kt += 16) {
        for (int idx = tid; idx < 1024; idx += 256) {
            int kk = idx & 15, m = idx >> 4, b = rowBase + m;
            As[kk * 64 + m] = d_subE[((size_t)(n * 1024 + b)) * 1152 + kt + kk];
            int cc = idx & 63, k2 = idx >> 6, c = colBase + cc;
            Bs[k2 * 64 + cc] = d_subW[n * 147456 + (kt + k2) * 128 + c];
        }
        __syncthreads();
#pragma unroll
        for (int k = 0; k < 16; k++) {
            float4 a = *(const float4*)&As[k * 64 + r0];
            float4 bb = *(const float4*)&Bs[k * 64 + c0];
            float av[4] = {a.x, a.y, a.z, a.w}, bv[4] = {bb.x, bb.y, bb.z, bb.w};
#pragma unroll
            for (int i = 0; i < 4; i++)
#pragma unroll
                for (int j = 0; j < 4; j++) acc[i][j] += av[i] * bv[j];
        }
        __syncthreads();
    }
#pragma unroll
    for (int i = 0; i < 4; i++)
#pragma unroll
        for (int j = 0; j < 4; j++) {
            int b = rowBase + r0 + i, o = colBase + c0 + j;
            float v = acc[i][j] * d_sigw[b * 3 + n];
            d_agg[b * 384 + n * 128 + o] = v;
            out_ss[n * 131072 + b * 128 + o] =
                subk[n * 256 + o] * v + ss[n * 131072 + b * 128 + o] * subk[n * 256 + 128 + o];
        }
}

// ---------- K9: x_o GEMM + final c, h ----------
__global__ __launch_bounds__(256) void k_final(const float* __restrict__ aw, const float* __restrict__ ab,
                                               const float* __restrict__ c0p, float* __restrict__ out) {
    __shared__ float As[16 * 64], Bs[16 * 64];
    int tid = threadIdx.x;
    int rowBase = blockIdx.y * 64, colBase = blockIdx.x * 64;
    int r0 = (tid >> 4) * 4, cc0 = (tid & 15) * 4;
    float acc[4][4] = {};
    for (int kt = 0; kt < 384; kt += 16) {
        for (int idx = tid; idx < 1024; idx += 256) {
            int kk = idx & 15, m = idx >> 4;
            As[kk * 64 + m] = d_agg[(rowBase + m) * 384 + kt + kk];
            int cc = idx & 63, k2 = idx >> 6;
            Bs[k2 * 64 + cc] = aw[(kt + k2) * 512 + colBase + cc];
        }
        __syncthreads();
#pragma unroll
        for (int k = 0; k < 16; k++) {
            float4 a = *(const float4*)&As[k * 64 + r0];
            float4 bb = *(const float4*)&Bs[k * 64 + cc0];
            float av[4] = {a.x, a.y, a.z, a.w}, bv[4] = {bb.x, bb.y, bb.z, bb.w};
#pragma unroll
            for (int i = 0; i < 4; i++)
#pragma unroll
                for (int j = 0; j < 4; j++) acc[i][j] += av[i] * bv[j];
        }
        __syncthreads();
    }
#pragma unroll
    for (int i = 0; i < 4; i++)
#pragma unroll
        for (int j = 0; j < 4; j++) {
            int b = rowBase + r0 + i, c = colBase + cc0 + j;
            float xo = sigm(acc[i][j] + ab[c]);
            float zi = d_z[b * 1536 + c];
            float zf = d_z[b * 1536 + 512 + c];
            float zc = d_z[b * 1536 + 1024 + c];
            float cv = zf * c0p[b * 512 + c] + zi * zc;
            out[b * 512 + c] = xo * tanhf(cv);
            out[B_ * U_ + b * 512 + c] = cv;
        }
}

// ---------- launch ----------
extern "C" void kernel_launch(void* const* d_in, const int* in_sizes, int n_in,
                              void* d_out, int out_size) {
    const float* inputs   = (const float*)d_in[0];
    const float* h0       = (const float*)d_in[1];
    const float* c0       = (const float*)d_in[2];
    const float* sub_st   = (const float*)d_in[3];
    const float* kern     = (const float*)d_in[4];
    const float* rkern    = (const float*)d_in[5];
    const float* bias     = (const float*)d_in[6];
    const float* sub_k    = (const float*)d_in[7];
    const float* sub_rki  = (const float*)d_in[8];
    const float* sub_rks  = (const float*)d_in[9];
    const float* agg_w    = (const float*)d_in[10];
    const float* agg_b    = (const float*)d_in[11];
    const float* sub_lng  = (const float*)d_in[12];
    const float* sub_lnb  = (const float*)d_in[13];
    const float* sub_bw   = (const float*)d_in[14];
    const float* sub_sw   = (const float*)d_in[15];
    const float* g_skw    = (const float*)d_in[16];
    const float* g_skb    = (const float*)d_in[17];
    const float* k1_lng   = (const float*)d_in[18];
    const float* k1_lnb   = (const float*)d_in[19];
    const float* k1_base  = (const float*)d_in[20];
    const float* k1_spl   = (const float*)d_in[21];
    const float* k2_lng   = (const float*)d_in[22];
    const float* k2_lnb   = (const float*)d_in[23];
    const float* k2_base  = (const float*)d_in[24];
    const float* k2_spl   = (const float*)d_in[25];
    const float* gw       = (const float*)d_in[26];
    const float* gb       = (const float*)d_in[27];
    const float* sw       = (const float*)d_in[28];
    const float* sb       = (const float*)d_in[29];
    const float* lg       = (const float*)d_in[30];
    const float* lb       = (const float*)d_in[31];
    float* out = (float*)d_out;

    static bool attr_set = false;
    if (!attr_set) {
        cudaFuncSetAttribute(k_mma, cudaFuncAttributeMaxDynamicSharedMemorySize, SM_MMA);
        attr_set = true;
    }

    k_stats<<<B_, 128>>>(inputs, g_skw, g_skb);
    k_mma<<<dim3(8, 8, 4), 256, SM_MMA>>>(inputs, k1_lng, k1_lnb, k1_base, k1_spl);
    k_head<<<B_, 128>>>(k2_lng, k2_lnb, k2_base, k2_spl, gw, gb, sw, sb, lg, lb);
    k_z<<<dim3(12, 8), 256>>>(inputs, h0, kern, rkern, bias);
    k_aggin<<<dim3(2, 16, 3), 256>>>(inputs, sub_st, sub_rki, sub_rks);
    k_subexpand<<<3 * B_, 128>>>(sub_lng, sub_lnb);
    k_packW<<<(3 * 1152 * 128 + 255) / 256, 256>>>(sub_bw, sub_sw);
    k_subgemm<<<dim3(2, 16, 3), 256>>>(sub_st, sub_k, out + 2 * B_ * U_);
    k_final<<<dim3(8, 16), 256>>>(agg_w, agg_b, c0, out);
}

// round 13
// speedup vs baseline: 1.3888x; 1.0248x over previous
#include <cuda_runtime.h>
#include <cuda_bf16.h>
#include <stdint.h>

#define DEV __device__ __forceinline__
typedef unsigned long long ull;

#define B_ 1024
#define U_ 512
#define SIGD 16512

// ---------- scratch ----------
__device__ float d_skip[B_ * 3];
__device__ float d_sigw[B_ * 3];
__device__ __align__(16) float d_z[B_ * 1536];
__device__ __align__(16) float d_aggin[3 * B_ * 128];
__device__ __align__(16) float d_subE[3 * B_ * 1152];
__device__ __align__(16) float d_subW[3 * 1152 * 128];
__device__ __align__(16) float d_agg[B_ * 384];
__device__ __align__(16) float d_part[8 * B_ * U_];

// ---------- helpers ----------
DEV float sigm(float x) { return 1.f / (1.f + __expf(-x)); }
DEV uint32_t f2tf(float f) {
    uint32_t r;
    asm("cvt.rna.tf32.f32 %0,%1;" : "=r"(r) : "f"(f));
    return r;
}
DEV void mma_tf32(float acc[4], const uint32_t a[4], const uint32_t b[2]) {
    asm volatile(
        "mma.sync.aligned.m16n8k8.row.col.f32.tf32.tf32.f32 "
        "{%0,%1,%2,%3},{%4,%5,%6,%7},{%8,%9},{%0,%1,%2,%3};"
        : "+f"(acc[0]), "+f"(acc[1]), "+f"(acc[2]), "+f"(acc[3])
        : "r"(a[0]), "r"(a[1]), "r"(a[2]), "r"(a[3]), "r"(b[0]), "r"(b[1]));
}

DEV void kan_expand(float xn, float e[9]) {
    e[0] = xn * sigm(xn);
#pragma unroll
    for (int j = 1; j < 9; j++) e[j] = 0.f;
    float tp = (xn + 2.2f) * 2.5f;
    float tf = floorf(tp);
    if (tf >= 0.f && tf <= 10.f) {
        int t = (int)tf;
        float u = tp - tf, u2 = u * u, u3 = u2 * u, omu = 1.f - u;
        float v0 = omu * omu * omu * (1.f / 6.f);
        float v1 = (3.f * u3 - 6.f * u2 + 4.f) * (1.f / 6.f);
        float v2 = (-3.f * u3 + 3.f * u2 + 3.f * u + 1.f) * (1.f / 6.f);
        float v3 = u3 * (1.f / 6.f);
        if (t >= 3)           e[t - 2] = v0;
        if (t >= 2 && t <= 9) e[t - 1] = v1;
        if (t >= 1 && t <= 8) e[t]     = v2;
        if (t <= 7)           e[t + 1] = v3;
    }
}

DEV float red128s(float v, float* sh) {
    int t = threadIdx.x;
    sh[t] = v; __syncthreads();
#pragma unroll
    for (int s = 64; s > 0; s >>= 1) { if (t < s) sh[t] += sh[t + s]; __syncthreads(); }
    float r = sh[0]; __syncthreads();
    return r;
}
DEV float red256s(float v, float* sh) {
    int t = threadIdx.x;
    sh[t] = v; __syncthreads();
#pragma unroll
    for (int s = 128; s > 0; s >>= 1) { if (t < s) sh[t] += sh[t + s]; __syncthreads(); }
    float r = sh[0]; __syncthreads();
    return r;
}

// =========================================================================
// K-MEGA: one launch = MMA blocks (0..255) + skip (256..1279) + z (1280..1375)
//         + aggin (1376..1471) + packW (1472..3199). 256 threads each.
// =========================================================================
#define LDA4 76
#define LDB4 136
// dynamic smem layout for MMA branch (words):
//   As4 [0, 9728) | Bs4 [9728, 19520) | lngS [19520, 21584) | lnbS [21584, 23648)
//   mus [23648, 23776) | rss [23776, 23904)
#define SM_MEGA (23904 * 4)   // 95616 bytes

// ---- MMA branch ----
DEV void mma_body(int bid, const float* __restrict__ x,
                  const float* __restrict__ lng, const float* __restrict__ lnb,
                  const float* __restrict__ wb, const float* __restrict__ ws,
                  uint32_t* sm4) {
    uint32_t* As4 = sm4;
    uint32_t* Bs4 = sm4 + 9728;
    float* lngS = (float*)(sm4 + 19520);
    float* lnbS = (float*)(sm4 + 21584);
    float* mus  = (float*)(sm4 + 23648);
    float* rss  = (float*)(sm4 + 23776);

    int tid = threadIdx.x, lane = tid & 31, wid = tid >> 5;
    int ks = bid & 7, mg = (bid >> 3) & 7, ng = bid >> 6;
    int rowBase = mg * 128, colBase = ng * 128;
    int warpRow = (wid & 3) * 32, warpCol = (wid >> 2) * 64;
    int g = lane >> 2, tg = lane & 3;
    int rsel = wid, n4 = lane * 4;
    int ksBase = ks * 2064;

    // --- in-CTA LN stats for this row block (closed form) ---
#pragma unroll 1
    for (int rr = 0; rr < 16; rr++) {
        int row = wid * 16 + rr;
        float4 v = *(const float4*)(x + (size_t)(rowBase + row) * 128 + lane * 4);
        float s = v.x + v.y + v.z + v.w;
        float q = v.x * v.x + v.y * v.y + v.z * v.z + v.w * v.w;
#pragma unroll
        for (int off = 16; off > 0; off >>= 1) {
            s += __shfl_xor_sync(0xFFFFFFFFu, s, off);
            q += __shfl_xor_sync(0xFFFFFFFFu, q, off);
        }
        if (lane == 0) {
            float mean = (s + 0.5f * s * s) / (float)SIGD;
            float m2 = (q + 0.25f * q * q) / (float)SIGD;
            mus[row] = mean;
            rss[row] = rsqrtf(m2 - mean * mean + 1e-3f);
        }
    }
    // --- stage lng/lnb split slice ---
    for (int i = tid; i < 2064; i += 256) {
        lngS[i] = lng[ksBase + i];
        lnbS[i] = lnb[ksBase + i];
    }
    __syncthreads();

    float acc[2][8][4];
#pragma unroll
    for (int mi = 0; mi < 2; mi++)
#pragma unroll
        for (int ni = 0; ni < 8; ni++)
#pragma unroll
            for (int q = 0; q < 4; q++) acc[mi][ni][q] = 0.f;

    for (int ch = 0; ch < 258; ch++) {
        int f0 = ksBase + ch * 8;
        int l0 = ch * 8;
        // --- A: expand 8 feats x 128 rows ---
#pragma unroll
        for (int p = 0; p < 4; p++) {
            int task = tid + p * 256;
            int fl = task & 7, row = task >> 3;
            int fg = f0 + fl;
            const float* xr = x + (size_t)(rowBase + row) * 128;
            float val;
            if (fg < 128) val = __ldg(xr + fg);
            else {
                int q = fg - 128;
                val = 0.5f * __ldg(xr + (q >> 7)) * __ldg(xr + (q & 127));
            }
            float xn = (val - mus[row]) * rss[row] * lngS[l0 + fl] + lnbS[l0 + fl];
            float e[9];
            kan_expand(xn, e);
            int off = row * LDA4 + fl * 9;
#pragma unroll
            for (int j = 0; j < 9; j++) As4[off + j] = f2tf(e[j]);
        }
        // --- B: load 72 x 128 fp32, cvt tf32, store [k][n] ---
#pragma unroll
        for (int i = 0; i < 9; i++) {
            int kl = i * 8 + rsel;
            int kg = f0 * 9 + kl;
            int f = kg / 9, jj = kg - f * 9;
            const float* p = (jj == 0) ? wb + (size_t)f * 512
                                       : ws + ((size_t)f * 8 + (jj - 1)) * 512;
            float4 v = *(const float4*)(p + colBase + n4);
            uint4 w;
            w.x = f2tf(v.x); w.y = f2tf(v.y); w.z = f2tf(v.z); w.w = f2tf(v.w);
            *(uint4*)&Bs4[kl * LDB4 + n4] = w;
        }
        __syncthreads();
        // --- MMA: 9 k-steps of 8 ---
#pragma unroll 3
        for (int ks2 = 0; ks2 < 9; ks2++) {
            int k0 = ks2 * 8;
            uint32_t aF[2][4];
#pragma unroll
            for (int mi = 0; mi < 2; mi++) {
                int r = warpRow + mi * 16;
                aF[mi][0] = As4[(r + g) * LDA4 + k0 + tg];
                aF[mi][1] = As4[(r + 8 + g) * LDA4 + k0 + tg];
                aF[mi][2] = As4[(r + g) * LDA4 + k0 + tg + 4];
                aF[mi][3] = As4[(r + 8 + g) * LDA4 + k0 + tg + 4];
            }
            uint32_t bF[8][2];
#pragma unroll
            for (int ni = 0; ni < 8; ni++) {
                int c = warpCol + ni * 8 + g;
                bF[ni][0] = Bs4[(k0 + tg) * LDB4 + c];
                bF[ni][1] = Bs4[(k0 + tg + 4) * LDB4 + c];
            }
#pragma unroll
            for (int mi = 0; mi < 2; mi++)
#pragma unroll
                for (int ni = 0; ni < 8; ni++)
                    mma_tf32(acc[mi][ni], aF[mi], bF[ni]);
        }
        __syncthreads();
    }
    float* dp = d_part + (size_t)ks * (B_ * U_);
#pragma unroll
    for (int mi = 0; mi < 2; mi++)
#pragma unroll
        for (int ni = 0; ni < 8; ni++) {
            int row = rowBase + warpRow + mi * 16 + g;
            int col = colBase + warpCol + ni * 8 + tg * 2;
            *(float2*)&dp[(size_t)row * 512 + col] = make_float2(acc[mi][ni][0], acc[mi][ni][1]);
            *(float2*)&dp[(size_t)(row + 8) * 512 + col] = make_float2(acc[mi][ni][2], acc[mi][ni][3]);
        }
}

// ---- skip branch (one row per block, 256 threads) ----
DEV void skip_body(int b, const float* __restrict__ x,
                   const float* __restrict__ skw, const float* __restrict__ skb,
                   uint32_t* sm4) {
    float* xs = (float*)sm4;       // 128
    float* sh = xs + 128;          // 256
    int t = threadIdx.x;
    if (t < 128) xs[t] = x[b * 128 + t];
    __syncthreads();
    float a0 = 0.f, a1 = 0.f, a2 = 0.f;
    for (int i = t; i < SIGD; i += 256) {
        float sv = (i < 128) ? xs[i] : 0.5f * xs[(i - 128) >> 7] * xs[(i - 128) & 127];
        a0 += sv * skw[i * 3 + 0];
        a1 += sv * skw[i * 3 + 1];
        a2 += sv * skw[i * 3 + 2];
    }
    a0 = red256s(a0, sh); a1 = red256s(a1, sh); a2 = red256s(a2, sh);
    if (t == 0) {
        d_skip[b * 3 + 0] = a0 + skb[0];
        d_skip[b * 3 + 1] = a1 + skb[1];
        d_skip[b * 3 + 2] = a2 + skb[2];
    }
}

// ---- z branch (tf32 MMA, 128x128 tile) ----
#define LDAZ 36
#define LDBZ 136
DEV void z_body(int zb, const float* __restrict__ x, const float* __restrict__ h0,
                const float* __restrict__ W1, const float* __restrict__ W2,
                const float* __restrict__ bias, uint32_t* sm4) {
    uint32_t* As4 = sm4;           // 128*36 = 4608
    uint32_t* Bs4 = sm4 + 4608;    // 32*136 = 4352
    int tid = threadIdx.x, lane = tid & 31, wid = tid >> 5;
    int colBase = (zb % 12) * 128, rowBase = (zb / 12) * 128;
    int warpRow = (wid & 3) * 32, warpCol = (wid >> 2) * 64;
    int g = lane >> 2, tg = lane & 3;
    int rsel = wid, n4 = lane * 4;
    int arow = tid >> 1, ahalf = tid & 1;

    float acc[2][8][4];
#pragma unroll
    for (int mi = 0; mi < 2; mi++)
#pragma unroll
        for (int ni = 0; ni < 8; ni++)
#pragma unroll
            for (int q = 0; q < 4; q++) acc[mi][ni][q] = 0.f;

    for (int kt = 0; kt < 640; kt += 32) {
        const float* src = (kt < 128) ? x + (size_t)(rowBase + arow) * 128 + kt + ahalf * 16
                                      : h0 + (size_t)(rowBase + arow) * 512 + (kt - 128) + ahalf * 16;
#pragma unroll
        for (int q = 0; q < 4; q++) {
            float4 v = *(const float4*)(src + q * 4);
            uint4 w;
            w.x = f2tf(v.x); w.y = f2tf(v.y); w.z = f2tf(v.z); w.w = f2tf(v.w);
            *(uint4*)&As4[arow * LDAZ + ahalf * 16 + q * 4] = w;
        }
#pragma unroll
        for (int i = 0; i < 4; i++) {
            int kl = i * 8 + rsel;
            int kg = kt + kl;
            const float* p = (kg < 128) ? W1 + (size_t)kg * 1536 + colBase + n4
                                        : W2 + (size_t)(kg - 128) * 1536 + colBase + n4;
            float4 v = *(const float4*)p;
            uint4 w;
            w.x = f2tf(v.x); w.y = f2tf(v.y); w.z = f2tf(v.z); w.w = f2tf(v.w);
            *(uint4*)&Bs4[kl * LDBZ + n4] = w;
        }
        __syncthreads();
#pragma unroll
        for (int ks2 = 0; ks2 < 4; ks2++) {
            int k0 = ks2 * 8;
            uint32_t aF[2][4];
#pragma unroll
            for (int mi = 0; mi < 2; mi++) {
                int r = warpRow + mi * 16;
                aF[mi][0] = As4[(r + g) * LDAZ + k0 + tg];
                aF[mi][1] = As4[(r + 8 + g) * LDAZ + k0 + tg];
                aF[mi][2] = As4[(r + g) * LDAZ + k0 + tg + 4];
                aF[mi][3] = As4[(r + 8 + g) * LDAZ + k0 + tg + 4];
            }
            uint32_t bF[8][2];
#pragma unroll
            for (int ni = 0; ni < 8; ni++) {
                int c = warpCol + ni * 8 + g;
                bF[ni][0] = Bs4[(k0 + tg) * LDBZ + c];
                bF[ni][1] = Bs4[(k0 + tg + 4) * LDBZ + c];
            }
#pragma unroll
            for (int mi = 0; mi < 2; mi++)
#pragma unroll
                for (int ni = 0; ni < 8; ni++)
                    mma_tf32(acc[mi][ni], aF[mi], bF[ni]);
        }
        __syncthreads();
    }
#pragma unroll
    for (int mi = 0; mi < 2; mi++)
#pragma unroll
        for (int ni = 0; ni < 8; ni++) {
            int row = rowBase + warpRow + mi * 16 + g;
            int col = colBase + warpCol + ni * 8 + tg * 2;
            d_z[(size_t)row * 1536 + col]     = sigm(acc[mi][ni][0] + bias[col]);
            d_z[(size_t)row * 1536 + col + 1] = sigm(acc[mi][ni][1] + bias[col + 1]);
            d_z[(size_t)(row + 8) * 1536 + col]     = sigm(acc[mi][ni][2] + bias[col]);
            d_z[(size_t)(row + 8) * 1536 + col + 1] = sigm(acc[mi][ni][3] + bias[col + 1]);
        }
}

// ---- aggin branch (scalar 64x64 tile) ----
DEV void aggin_body(int ab, const float* __restrict__ x, const float* __restrict__ ss,
                    const float* __restrict__ rki, const float* __restrict__ rks,
                    uint32_t* sm4) {
    float* As = (float*)sm4;       // 16*64
    float* Bs = As + 1024;         // 16*64
    int tid = threadIdx.x;
    int n = ab / 32, yg = (ab / 2) % 16, xg = ab & 1;
    int rowBase = yg * 64, colBase = xg * 64;
    int r0 = (tid >> 4) * 4, c0 = (tid & 15) * 4;
    float acc[4][4] = {};
    for (int kt = 0; kt < 256; kt += 16) {
        for (int idx = tid; idx < 1024; idx += 256) {
            int kk = idx & 15, m = idx >> 4, kg = kt + kk, b = rowBase + m;
            As[kk * 64 + m] = (kg < 128) ? x[b * 128 + kg] : ss[n * 131072 + b * 128 + kg - 128];
            int cc = idx & 63, k2 = idx >> 6, kg2 = kt + k2, c = colBase + cc;
            Bs[k2 * 64 + cc] = (kg2 < 128) ? rki[n * 16384 + kg2 * 128 + c]
                                           : rks[n * 16384 + (kg2 - 128) * 128 + c];
        }
        __syncthreads();
#pragma unroll
        for (int k = 0; k < 16; k++) {
            float4 a = *(const float4*)&As[k * 64 + r0];
            float4 bb = *(const float4*)&Bs[k * 64 + c0];
            float av[4] = {a.x, a.y, a.z, a.w}, bv[4] = {bb.x, bb.y, bb.z, bb.w};
#pragma unroll
            for (int i = 0; i < 4; i++)
#pragma unroll
                for (int j = 0; j < 4; j++) acc[i][j] += av[i] * bv[j];
        }
        __syncthreads();
    }
#pragma unroll
    for (int i = 0; i < 4; i++)
#pragma unroll
        for (int j = 0; j < 4; j++)
            d_aggin[n * 131072 + (rowBase + r0 + i) * 128 + colBase + c0 + j] = acc[i][j];
}

// ---- packW branch ----
DEV void packW_body(int pb, const float* __restrict__ bw, const float* __restrict__ sw) {
    int idx = pb * 256 + threadIdx.x;
    if (idx >= 3 * 1152 * 128) return;
    int n = idx / 147456, rem = idx - n * 147456;
    int k = rem >> 7, o = rem & 127;
    int f = k / 9, j = k - f * 9;
    d_subW[idx] = (j == 0) ? bw[n * 16384 + f * 128 + o]
                           : sw[n * 131072 + (f * 8 + j - 1) * 128 + o];
}

__global__ __launch_bounds__(256, 2) void k_mega(
    const float* __restrict__ x, const float* __restrict__ lng, const float* __restrict__ lnb,
    const float* __restrict__ wb, const float* __restrict__ ws,
    const float* __restrict__ skw, const float* __restrict__ skb,
    const float* __restrict__ h0, const float* __restrict__ W1, const float* __restrict__ W2,
    const float* __restrict__ bias,
    const float* __restrict__ ss, const float* __restrict__ rki, const float* __restrict__ rks,
    const float* __restrict__ bw, const float* __restrict__ sw) {
    extern __shared__ uint32_t sm4[];
    int bid = blockIdx.x;
    if (bid < 256)       mma_body(bid, x, lng, lnb, wb, ws, sm4);
    else if (bid < 1280) skip_body(bid - 256, x, skw, skb, sm4);
    else if (bid < 1376) z_body(bid - 1280, x, h0, W1, W2, bias, sm4);
    else if (bid < 1472) aggin_body(bid - 1376, x, ss, rki, rks, sm4);
    else                 packW_body(bid - 1472, bw, sw);
}

// =========================================================================
// K-MID: head (0..1023) + subexpand (1024..4095), 128 threads
// =========================================================================
DEV void head_body(int b, const float* g2g, const float* g2b,
                   const float* k2base, const float* k2spl,
                   const float* gw, const float* gb, const float* sw2, const float* sb,
                   const float* lg, const float* lb, float* sh) {
    int t = threadIdx.x;
    float v[4], S = 0.f, Q = 0.f;
#pragma unroll
    for (int m = 0; m < 4; m++) {
        float s = 0.f;
#pragma unroll
        for (int ks = 0; ks < 8; ks++)
            s += d_part[(size_t)ks * (B_ * U_) + b * 512 + t + 128 * m];
        v[m] = s;
        S += s; Q += s * s;
    }
    S = red128s(S, sh); Q = red128s(Q, sh);
    float mean = S / 512.f;
    float rstd = rsqrtf(Q / 512.f - mean * mean + 1e-3f);
    float a0 = 0.f, a1 = 0.f, a2 = 0.f;
#pragma unroll
    for (int m = 0; m < 4; m++) {
        int i = t + 128 * m;
        float xn = (v[m] - mean) * rstd * g2g[i] + g2b[i];
        float e[9];
        kan_expand(xn, e);
        a0 += e[0] * k2base[i * 3 + 0];
        a1 += e[0] * k2base[i * 3 + 1];
        a2 += e[0] * k2base[i * 3 + 2];
#pragma unroll
        for (int j = 0; j < 8; j++) {
            const float* sp = k2spl + (size_t)(i * 8 + j) * 3;
            a0 += e[1 + j] * sp[0];
            a1 += e[1 + j] * sp[1];
            a2 += e[1 + j] * sp[2];
        }
    }
    a0 = red128s(a0, sh); a1 = red128s(a1, sh); a2 = red128s(a2, sh);
    if (t == 0) {
        float h2[3] = {a0, a1, a2};
        float y[3];
#pragma unroll
        for (int o = 0; o < 3; o++) {
            float g1 = gb[o], s1 = sb[o];
#pragma unroll
            for (int p = 0; p < 3; p++) { g1 += h2[p] * gw[p * 3 + o]; s1 += h2[p] * sw2[p * 3 + o]; }
            y[o] = d_skip[b * 3 + o] + g1 * sigm(s1);
        }
        float m = (y[0] + y[1] + y[2]) * (1.f / 3.f);
        float var = ((y[0] - m) * (y[0] - m) + (y[1] - m) * (y[1] - m) + (y[2] - m) * (y[2] - m)) * (1.f / 3.f);
        float rs = rsqrtf(var + 1e-3f);
        float yn[3], mx = -1e30f;
#pragma unroll
        for (int o = 0; o < 3; o++) { yn[o] = (y[o] - m) * rs * lg[o] + lb[o]; mx = fmaxf(mx, yn[o]); }
        float e0 = __expf(yn[0] - mx), e1 = __expf(yn[1] - mx), e2 = __expf(yn[2] - mx);
        float inv = 1.f / (e0 + e1 + e2);
        d_sigw[b * 3 + 0] = e0 * inv;
        d_sigw[b * 3 + 1] = e1 * inv;
        d_sigw[b * 3 + 2] = e2 * inv;
    }
}

DEV void subexpand_body(int bx, const float* lg, const float* lb, float* sh) {
    int t = threadIdx.x;
    int n = bx >> 10;
    float v = d_aggin[bx * 128 + t];
    float S = red128s(v, sh), Q = red128s(v * v, sh);
    float mean = S * (1.f / 128.f);
    float rstd = rsqrtf(Q * (1.f / 128.f) - mean * mean + 1e-3f);
    float xn = (v - mean) * rstd * lg[n * 128 + t] + lb[n * 128 + t];
    float e[9];
    kan_expand(xn, e);
    size_t base = (size_t)bx * 1152 + t * 9;
#pragma unroll
    for (int j = 0; j < 9; j++) d_subE[base + j] = e[j];
}

__global__ __launch_bounds__(128) void k_mid(
    const float* __restrict__ g2g, const float* __restrict__ g2b,
    const float* __restrict__ k2base, const float* __restrict__ k2spl,
    const float* __restrict__ gw, const float* __restrict__ gb,
    const float* __restrict__ sw2, const float* __restrict__ sb,
    const float* __restrict__ lg, const float* __restrict__ lb,
    const float* __restrict__ slg, const float* __restrict__ slb) {
    __shared__ float sh[128];
    int bid = blockIdx.x;
    if (bid < 1024) head_body(bid, g2g, g2b, k2base, k2spl, gw, gb, sw2, sb, lg, lb, sh);
    else            subexpand_body(bid - 1024, slg, slb, sh);
}

// ---------- K8: sub GEMM + epilogue ----------
__global__ __launch_bounds__(256) void k_subgemm(const float* __restrict__ ss,
                                                 const float* __restrict__ subk,
                                                 float* __restrict__ out_ss) {
    __shared__ float As[16 * 64], Bs[16 * 64];
    int tid = threadIdx.x, n = blockIdx.z;
    int rowBase = blockIdx.y * 64, colBase = blockIdx.x * 64;
    int r0 = (tid >> 4) * 4, c0 = (tid & 15) * 4;
    float acc[4][4] = {};
    for (int kt = 0; kt < 1152; kt += 16) {
        for (int idx = tid; idx < 1024; idx += 256) {
            int kk = idx & 15, m = idx >> 4, b = rowBase + m;
            As[kk * 64 + m] = d_subE[((size_t)(n * 1024 + b)) * 1152 + kt + kk];
            int cc = idx & 63, k2 = idx >> 6, c = colBase + cc;
            Bs[k2 * 64 + cc] = d_subW[n * 147456 + (kt + k2) * 128 + c];
        }
        __syncthreads();
#pragma unroll
        for (int k = 0; k < 16; k++) {
            float4 a = *(const float4*)&As[k * 64 + r0];
            float4 bb = *(const float4*)&Bs[k * 64 + c0];
            float av[4] = {a.x, a.y, a.z, a.w}, bv[4] = {bb.x, bb.y, bb.z, bb.w};
#pragma unroll
            for (int i = 0; i < 4; i++)
#pragma unroll
                for (int j = 0; j < 4; j++) acc[i][j] += av[i] * bv[j];
        }
        __syncthreads();
    }
#pragma unroll
    for (int i = 0; i < 4; i++)
#pragma unroll
        for (int j = 0; j < 4; j++) {
            int b = rowBase + r0 + i, o = colBase + c0 + j;
            float v = acc[i][j] * d_sigw[b * 3 + n];
            d_agg[b * 384 + n * 128 + o] = v;
            out_ss[n * 131072 + b * 128 + o] =
                subk[n * 256 + o] * v + ss[n * 131072 + b * 128 + o] * subk[n * 256 + 128 + o];
        }
}

// ---------- K9: x_o GEMM + final c, h ----------
__global__ __launch_bounds__(256) void k_final(const float* __restrict__ aw, const float* __restrict__ ab,
                                               const float* __restrict__ c0p, float* __restrict__ out) {
    __shared__ float As[16 * 64], Bs[16 * 64];
    int tid = threadIdx.x;
    int rowBase = blockIdx.y * 64, colBase = blockIdx.x * 64;
    int r0 = (tid >> 4) * 4, cc0 = (tid & 15) * 4;
    float acc[4][4] = {};
    for (int kt = 0; kt < 384; kt += 16) {
        for (int idx = tid; idx < 1024; idx += 256) {
            int kk = idx & 15, m = idx >> 4;
            As[kk * 64 + m] = d_agg[(rowBase + m) * 384 + kt + kk];
            int cc = idx & 63, k2 = idx >> 6;
            Bs[k2 * 64 + cc] = aw[(kt + k2) * 512 + colBase + cc];
        }
        __syncthreads();
#pragma unroll
        for (int k = 0; k < 16; k++) {
            float4 a = *(const float4*)&As[k * 64 + r0];
            float4 bb = *(const float4*)&Bs[k * 64 + cc0];
            float av[4] = {a.x, a.y, a.z, a.w}, bv[4] = {bb.x, bb.y, bb.z, bb.w};
#pragma unroll
            for (int i = 0; i < 4; i++)
#pragma unroll
                for (int j = 0; j < 4; j++) acc[i][j] += av[i] * bv[j];
        }
        __syncthreads();
    }
#pragma unroll
    for (int i = 0; i < 4; i++)
#pragma unroll
        for (int j = 0; j < 4; j++) {
            int b = rowBase + r0 + i, c = colBase + cc0 + j;
            float xo = sigm(acc[i][j] + ab[c]);
            float zi = d_z[b * 1536 + c];
            float zf = d_z[b * 1536 + 512 + c];
            float zc = d_z[b * 1536 + 1024 + c];
            float cv = zf * c0p[b * 512 + c] + zi * zc;
            out[b * 512 + c] = xo * tanhf(cv);
            out[B_ * U_ + b * 512 + c] = cv;
        }
}

// ---------- launch ----------
extern "C" void kernel_launch(void* const* d_in, const int* in_sizes, int n_in,
                              void* d_out, int out_size) {
    const float* inputs   = (const float*)d_in[0];
    const float* h0       = (const float*)d_in[1];
    const float* c0       = (const float*)d_in[2];
    const float* sub_st   = (const float*)d_in[3];
    const float* kern     = (const float*)d_in[4];
    const float* rkern    = (const float*)d_in[5];
    const float* bias     = (const float*)d_in[6];
    const float* sub_k    = (const float*)d_in[7];
    const float* sub_rki  = (const float*)d_in[8];
    const float* sub_rks  = (const float*)d_in[9];
    const float* agg_w    = (const float*)d_in[10];
    const float* agg_b    = (const float*)d_in[11];
    const float* sub_lng  = (const float*)d_in[12];
    const float* sub_lnb  = (const float*)d_in[13];
    const float* sub_bw   = (const float*)d_in[14];
    const float* sub_sw   = (const float*)d_in[15];
    const float* g_skw    = (const float*)d_in[16];
    const float* g_skb    = (const float*)d_in[17];
    const float* k1_lng   = (const float*)d_in[18];
    const float* k1_lnb   = (const float*)d_in[19];
    const float* k1_base  = (const float*)d_in[20];
    const float* k1_spl   = (const float*)d_in[21];
    const float* k2_lng   = (const float*)d_in[22];
    const float* k2_lnb   = (const float*)d_in[23];
    const float* k2_base  = (const float*)d_in[24];
    const float* k2_spl   = (const float*)d_in[25];
    const float* gw       = (const float*)d_in[26];
    const float* gb       = (const float*)d_in[27];
    const float* sw       = (const float*)d_in[28];
    const float* sb       = (const float*)d_in[29];
    const float* lg       = (const float*)d_in[30];
    const float* lb       = (const float*)d_in[31];
    float* out = (float*)d_out;

    static bool attr_set = false;
    if (!attr_set) {
        cudaFuncSetAttribute(k_mega, cudaFuncAttributeMaxDynamicSharedMemorySize, SM_MEGA);
        attr_set = true;
    }

    k_mega<<<3200, 256, SM_MEGA>>>(inputs, k1_lng, k1_lnb, k1_base, k1_spl,
                                   g_skw, g_skb, h0, kern, rkern, bias,
                                   sub_st, sub_rki, sub_rks, sub_bw, sub_sw);
    k_mid<<<4096, 128>>>(k2_lng, k2_lnb, k2_base, k2_spl, gw, gb, sw, sb, lg, lb,
                         sub_lng, sub_lnb);
    k_subgemm<<<dim3(2, 16, 3), 256>>>(sub_st, sub_k, out + 2 * B_ * U_);
    k_final<<<dim3(8, 16), 256>>>(agg_w, agg_b, c0, out);
}

// round 14
// speedup vs baseline: 1.4944x; 1.0760x over previous
#include <cuda_runtime.h>
#include <cuda_bf16.h>
#include <stdint.h>

#define DEV __device__ __forceinline__
typedef unsigned long long ull;

#define B_ 1024
#define U_ 512
#define SIGD 16512

// ---------- scratch ----------
__device__ float d_skip[B_ * 3];
__device__ float d_sigw[B_ * 3];
__device__ __align__(16) float d_z[B_ * 1536];
__device__ __align__(16) float d_aggin[3 * B_ * 128];
__device__ __align__(16) float d_subE[3 * B_ * 1152];
__device__ __align__(16) float d_subW[3 * 1152 * 128];
__device__ __align__(16) float d_agg[B_ * 384];
__device__ __align__(16) float d_part[8 * B_ * U_];

// ---------- helpers ----------
DEV float sigm(float x) { return 1.f / (1.f + __expf(-x)); }
DEV uint32_t f2tf(float f) {
    uint32_t r;
    asm("cvt.rna.tf32.f32 %0,%1;" : "=r"(r) : "f"(f));
    return r;
}
DEV void mma_tf32(float acc[4], const uint32_t a[4], const uint32_t b[2]) {
    asm volatile(
        "mma.sync.aligned.m16n8k8.row.col.f32.tf32.tf32.f32 "
        "{%0,%1,%2,%3},{%4,%5,%6,%7},{%8,%9},{%0,%1,%2,%3};"
        : "+f"(acc[0]), "+f"(acc[1]), "+f"(acc[2]), "+f"(acc[3])
        : "r"(a[0]), "r"(a[1]), "r"(a[2]), "r"(a[3]), "r"(b[0]), "r"(b[1]));
}

DEV void kan_expand(float xn, float e[9]) {
    e[0] = xn * sigm(xn);
#pragma unroll
    for (int j = 1; j < 9; j++) e[j] = 0.f;
    float tp = (xn + 2.2f) * 2.5f;
    float tf = floorf(tp);
    if (tf >= 0.f && tf <= 10.f) {
        int t = (int)tf;
        float u = tp - tf, u2 = u * u, u3 = u2 * u, omu = 1.f - u;
        float v0 = omu * omu * omu * (1.f / 6.f);
        float v1 = (3.f * u3 - 6.f * u2 + 4.f) * (1.f / 6.f);
        float v2 = (-3.f * u3 + 3.f * u2 + 3.f * u + 1.f) * (1.f / 6.f);
        float v3 = u3 * (1.f / 6.f);
        if (t >= 3)           e[t - 2] = v0;
        if (t >= 2 && t <= 9) e[t - 1] = v1;
        if (t >= 1 && t <= 8) e[t]     = v2;
        if (t <= 7)           e[t + 1] = v3;
    }
}

DEV float red128s(float v, float* sh) {
    int t = threadIdx.x;
    sh[t] = v; __syncthreads();
#pragma unroll
    for (int s = 64; s > 0; s >>= 1) { if (t < s) sh[t] += sh[t + s]; __syncthreads(); }
    float r = sh[0]; __syncthreads();
    return r;
}
DEV float red256s(float v, float* sh) {
    int t = threadIdx.x;
    sh[t] = v; __syncthreads();
#pragma unroll
    for (int s = 128; s > 0; s >>= 1) { if (t < s) sh[t] += sh[t + s]; __syncthreads(); }
    float r = sh[0]; __syncthreads();
    return r;
}

// =========================================================================
// K-MEGA (unchanged from R12): MMA (0..255) + skip (256..1279) + z (1280..1375)
//         + aggin (1376..1471) + packW (1472..3199)
// =========================================================================
#define LDA4 76
#define LDB4 136
#define SM_MEGA (23904 * 4)   // 95616 bytes

DEV void mma_body(int bid, const float* __restrict__ x,
                  const float* __restrict__ lng, const float* __restrict__ lnb,
                  const float* __restrict__ wb, const float* __restrict__ ws,
                  uint32_t* sm4) {
    uint32_t* As4 = sm4;
    uint32_t* Bs4 = sm4 + 9728;
    float* lngS = (float*)(sm4 + 19520);
    float* lnbS = (float*)(sm4 + 21584);
    float* mus  = (float*)(sm4 + 23648);
    float* rss  = (float*)(sm4 + 23776);

    int tid = threadIdx.x, lane = tid & 31, wid = tid >> 5;
    int ks = bid & 7, mg = (bid >> 3) & 7, ng = bid >> 6;
    int rowBase = mg * 128, colBase = ng * 128;
    int warpRow = (wid & 3) * 32, warpCol = (wid >> 2) * 64;
    int g = lane >> 2, tg = lane & 3;
    int rsel = wid, n4 = lane * 4;
    int ksBase = ks * 2064;

#pragma unroll 1
    for (int rr = 0; rr < 16; rr++) {
        int row = wid * 16 + rr;
        float4 v = *(const float4*)(x + (size_t)(rowBase + row) * 128 + lane * 4);
        float s = v.x + v.y + v.z + v.w;
        float q = v.x * v.x + v.y * v.y + v.z * v.z + v.w * v.w;
#pragma unroll
        for (int off = 16; off > 0; off >>= 1) {
            s += __shfl_xor_sync(0xFFFFFFFFu, s, off);
            q += __shfl_xor_sync(0xFFFFFFFFu, q, off);
        }
        if (lane == 0) {
            float mean = (s + 0.5f * s * s) / (float)SIGD;
            float m2 = (q + 0.25f * q * q) / (float)SIGD;
            mus[row] = mean;
            rss[row] = rsqrtf(m2 - mean * mean + 1e-3f);
        }
    }
    for (int i = tid; i < 2064; i += 256) {
        lngS[i] = lng[ksBase + i];
        lnbS[i] = lnb[ksBase + i];
    }
    __syncthreads();

    float acc[2][8][4];
#pragma unroll
    for (int mi = 0; mi < 2; mi++)
#pragma unroll
        for (int ni = 0; ni < 8; ni++)
#pragma unroll
            for (int q = 0; q < 4; q++) acc[mi][ni][q] = 0.f;

    for (int ch = 0; ch < 258; ch++) {
        int f0 = ksBase + ch * 8;
        int l0 = ch * 8;
#pragma unroll
        for (int p = 0; p < 4; p++) {
            int task = tid + p * 256;
            int fl = task & 7, row = task >> 3;
            int fg = f0 + fl;
            const float* xr = x + (size_t)(rowBase + row) * 128;
            float val;
            if (fg < 128) val = __ldg(xr + fg);
            else {
                int q = fg - 128;
                val = 0.5f * __ldg(xr + (q >> 7)) * __ldg(xr + (q & 127));
            }
            float xn = (val - mus[row]) * rss[row] * lngS[l0 + fl] + lnbS[l0 + fl];
            float e[9];
            kan_expand(xn, e);
            int off = row * LDA4 + fl * 9;
#pragma unroll
            for (int j = 0; j < 9; j++) As4[off + j] = f2tf(e[j]);
        }
#pragma unroll
        for (int i = 0; i < 9; i++) {
            int kl = i * 8 + rsel;
            int kg = f0 * 9 + kl;
            int f = kg / 9, jj = kg - f * 9;
            const float* p = (jj == 0) ? wb + (size_t)f * 512
                                       : ws + ((size_t)f * 8 + (jj - 1)) * 512;
            float4 v = *(const float4*)(p + colBase + n4);
            uint4 w;
            w.x = f2tf(v.x); w.y = f2tf(v.y); w.z = f2tf(v.z); w.w = f2tf(v.w);
            *(uint4*)&Bs4[kl * LDB4 + n4] = w;
        }
        __syncthreads();
#pragma unroll 3
        for (int ks2 = 0; ks2 < 9; ks2++) {
            int k0 = ks2 * 8;
            uint32_t aF[2][4];
#pragma unroll
            for (int mi = 0; mi < 2; mi++) {
                int r = warpRow + mi * 16;
                aF[mi][0] = As4[(r + g) * LDA4 + k0 + tg];
                aF[mi][1] = As4[(r + 8 + g) * LDA4 + k0 + tg];
                aF[mi][2] = As4[(r + g) * LDA4 + k0 + tg + 4];
                aF[mi][3] = As4[(r + 8 + g) * LDA4 + k0 + tg + 4];
            }
            uint32_t bF[8][2];
#pragma unroll
            for (int ni = 0; ni < 8; ni++) {
                int c = warpCol + ni * 8 + g;
                bF[ni][0] = Bs4[(k0 + tg) * LDB4 + c];
                bF[ni][1] = Bs4[(k0 + tg + 4) * LDB4 + c];
            }
#pragma unroll
            for (int mi = 0; mi < 2; mi++)
#pragma unroll
                for (int ni = 0; ni < 8; ni++)
                    mma_tf32(acc[mi][ni], aF[mi], bF[ni]);
        }
        __syncthreads();
    }
    float* dp = d_part + (size_t)ks * (B_ * U_);
#pragma unroll
    for (int mi = 0; mi < 2; mi++)
#pragma unroll
        for (int ni = 0; ni < 8; ni++) {
            int row = rowBase + warpRow + mi * 16 + g;
            int col = colBase + warpCol + ni * 8 + tg * 2;
            *(float2*)&dp[(size_t)row * 512 + col] = make_float2(acc[mi][ni][0], acc[mi][ni][1]);
            *(float2*)&dp[(size_t)(row + 8) * 512 + col] = make_float2(acc[mi][ni][2], acc[mi][ni][3]);
        }
}

DEV void skip_body(int b, const float* __restrict__ x,
                   const float* __restrict__ skw, const float* __restrict__ skb,
                   uint32_t* sm4) {
    float* xs = (float*)sm4;
    float* sh = xs + 128;
    int t = threadIdx.x;
    if (t < 128) xs[t] = x[b * 128 + t];
    __syncthreads();
    float a0 = 0.f, a1 = 0.f, a2 = 0.f;
    for (int i = t; i < SIGD; i += 256) {
        float sv = (i < 128) ? xs[i] : 0.5f * xs[(i - 128) >> 7] * xs[(i - 128) & 127];
        a0 += sv * skw[i * 3 + 0];
        a1 += sv * skw[i * 3 + 1];
        a2 += sv * skw[i * 3 + 2];
    }
    a0 = red256s(a0, sh); a1 = red256s(a1, sh); a2 = red256s(a2, sh);
    if (t == 0) {
        d_skip[b * 3 + 0] = a0 + skb[0];
        d_skip[b * 3 + 1] = a1 + skb[1];
        d_skip[b * 3 + 2] = a2 + skb[2];
    }
}

#define LDAZ 36
#define LDBZ 136
DEV void z_body(int zb, const float* __restrict__ x, const float* __restrict__ h0,
                const float* __restrict__ W1, const float* __restrict__ W2,
                const float* __restrict__ bias, uint32_t* sm4) {
    uint32_t* As4 = sm4;
    uint32_t* Bs4 = sm4 + 4608;
    int tid = threadIdx.x, lane = tid & 31, wid = tid >> 5;
    int colBase = (zb % 12) * 128, rowBase = (zb / 12) * 128;
    int warpRow = (wid & 3) * 32, warpCol = (wid >> 2) * 64;
    int g = lane >> 2, tg = lane & 3;
    int rsel = wid, n4 = lane * 4;
    int arow = tid >> 1, ahalf = tid & 1;

    float acc[2][8][4];
#pragma unroll
    for (int mi = 0; mi < 2; mi++)
#pragma unroll
        for (int ni = 0; ni < 8; ni++)
#pragma unroll
            for (int q = 0; q < 4; q++) acc[mi][ni][q] = 0.f;

    for (int kt = 0; kt < 640; kt += 32) {
        const float* src = (kt < 128) ? x + (size_t)(rowBase + arow) * 128 + kt + ahalf * 16
                                      : h0 + (size_t)(rowBase + arow) * 512 + (kt - 128) + ahalf * 16;
#pragma unroll
        for (int q = 0; q < 4; q++) {
            float4 v = *(const float4*)(src + q * 4);
            uint4 w;
            w.x = f2tf(v.x); w.y = f2tf(v.y); w.z = f2tf(v.z); w.w = f2tf(v.w);
            *(uint4*)&As4[arow * LDAZ + ahalf * 16 + q * 4] = w;
        }
#pragma unroll
        for (int i = 0; i < 4; i++) {
            int kl = i * 8 + rsel;
            int kg = kt + kl;
            const float* p = (kg < 128) ? W1 + (size_t)kg * 1536 + colBase + n4
                                        : W2 + (size_t)(kg - 128) * 1536 + colBase + n4;
            float4 v = *(const float4*)p;
            uint4 w;
            w.x = f2tf(v.x); w.y = f2tf(v.y); w.z = f2tf(v.z); w.w = f2tf(v.w);
            *(uint4*)&Bs4[kl * LDBZ + n4] = w;
        }
        __syncthreads();
#pragma unroll
        for (int ks2 = 0; ks2 < 4; ks2++) {
            int k0 = ks2 * 8;
            uint32_t aF[2][4];
#pragma unroll
            for (int mi = 0; mi < 2; mi++) {
                int r = warpRow + mi * 16;
                aF[mi][0] = As4[(r + g) * LDAZ + k0 + tg];
                aF[mi][1] = As4[(r + 8 + g) * LDAZ + k0 + tg];
                aF[mi][2] = As4[(r + g) * LDAZ + k0 + tg + 4];
                aF[mi][3] = As4[(r + 8 + g) * LDAZ + k0 + tg + 4];
            }
            uint32_t bF[8][2];
#pragma unroll
            for (int ni = 0; ni < 8; ni++) {
                int c = warpCol + ni * 8 + g;
                bF[ni][0] = Bs4[(k0 + tg) * LDBZ + c];
                bF[ni][1] = Bs4[(k0 + tg + 4) * LDBZ + c];
            }
#pragma unroll
            for (int mi = 0; mi < 2; mi++)
#pragma unroll
                for (int ni = 0; ni < 8; ni++)
                    mma_tf32(acc[mi][ni], aF[mi], bF[ni]);
        }
        __syncthreads();
    }
#pragma unroll
    for (int mi = 0; mi < 2; mi++)
#pragma unroll
        for (int ni = 0; ni < 8; ni++) {
            int row = rowBase + warpRow + mi * 16 + g;
            int col = colBase + warpCol + ni * 8 + tg * 2;
            d_z[(size_t)row * 1536 + col]     = sigm(acc[mi][ni][0] + bias[col]);
            d_z[(size_t)row * 1536 + col + 1] = sigm(acc[mi][ni][1] + bias[col + 1]);
            d_z[(size_t)(row + 8) * 1536 + col]     = sigm(acc[mi][ni][2] + bias[col]);
            d_z[(size_t)(row + 8) * 1536 + col + 1] = sigm(acc[mi][ni][3] + bias[col + 1]);
        }
}

DEV void aggin_body(int ab, const float* __restrict__ x, const float* __restrict__ ss,
                    const float* __restrict__ rki, const float* __restrict__ rks,
                    uint32_t* sm4) {
    float* As = (float*)sm4;
    float* Bs = As + 1024;
    int tid = threadIdx.x;
    int n = ab / 32, yg = (ab / 2) % 16, xg = ab & 1;
    int rowBase = yg * 64, colBase = xg * 64;
    int r0 = (tid >> 4) * 4, c0 = (tid & 15) * 4;
    float acc[4][4] = {};
    for (int kt = 0; kt < 256; kt += 16) {
        for (int idx = tid; idx < 1024; idx += 256) {
            int kk = idx & 15, m = idx >> 4, kg = kt + kk, b = rowBase + m;
            As[kk * 64 + m] = (kg < 128) ? x[b * 128 + kg] : ss[n * 131072 + b * 128 + kg - 128];
            int cc = idx & 63, k2 = idx >> 6, kg2 = kt + k2, c = colBase + cc;
            Bs[k2 * 64 + cc] = (kg2 < 128) ? rki[n * 16384 + kg2 * 128 + c]
                                           : rks[n * 16384 + (kg2 - 128) * 128 + c];
        }
        __syncthreads();
#pragma unroll
        for (int k = 0; k < 16; k++) {
            float4 a = *(const float4*)&As[k * 64 + r0];
            float4 bb = *(const float4*)&Bs[k * 64 + c0];
            float av[4] = {a.x, a.y, a.z, a.w}, bv[4] = {bb.x, bb.y, bb.z, bb.w};
#pragma unroll
            for (int i = 0; i < 4; i++)
#pragma unroll
                for (int j = 0; j < 4; j++) acc[i][j] += av[i] * bv[j];
        }
        __syncthreads();
    }
#pragma unroll
    for (int i = 0; i < 4; i++)
#pragma unroll
        for (int j = 0; j < 4; j++)
            d_aggin[n * 131072 + (rowBase + r0 + i) * 128 + colBase + c0 + j] = acc[i][j];
}

DEV void packW_body(int pb, const float* __restrict__ bw, const float* __restrict__ sw) {
    int idx = pb * 256 + threadIdx.x;
    if (idx >= 3 * 1152 * 128) return;
    int n = idx / 147456, rem = idx - n * 147456;
    int k = rem >> 7, o = rem & 127;
    int f = k / 9, j = k - f * 9;
    d_subW[idx] = (j == 0) ? bw[n * 16384 + f * 128 + o]
                           : sw[n * 131072 + (f * 8 + j - 1) * 128 + o];
}

__global__ __launch_bounds__(256, 2) void k_mega(
    const float* __restrict__ x, const float* __restrict__ lng, const float* __restrict__ lnb,
    const float* __restrict__ wb, const float* __restrict__ ws,
    const float* __restrict__ skw, const float* __restrict__ skb,
    const float* __restrict__ h0, const float* __restrict__ W1, const float* __restrict__ W2,
    const float* __restrict__ bias,
    const float* __restrict__ ss, const float* __restrict__ rki, const float* __restrict__ rks,
    const float* __restrict__ bw, const float* __restrict__ sw) {
    extern __shared__ uint32_t sm4[];
    int bid = blockIdx.x;
    if (bid < 256)       mma_body(bid, x, lng, lnb, wb, ws, sm4);
    else if (bid < 1280) skip_body(bid - 256, x, skw, skb, sm4);
    else if (bid < 1376) z_body(bid - 1280, x, h0, W1, W2, bias, sm4);
    else if (bid < 1472) aggin_body(bid - 1376, x, ss, rki, rks, sm4);
    else                 packW_body(bid - 1472, bw, sw);
}

// =========================================================================
// K-MID: head (0..1023) + subexpand (1024..4095), 128 threads
// =========================================================================
DEV void head_body(int b, const float* g2g, const float* g2b,
                   const float* k2base, const float* k2spl,
                   const float* gw, const float* gb, const float* sw2, const float* sb,
                   const float* lg, const float* lb, float* sh) {
    int t = threadIdx.x;
    float v[4], S = 0.f, Q = 0.f;
#pragma unroll
    for (int m = 0; m < 4; m++) {
        float s = 0.f;
#pragma unroll
        for (int ks = 0; ks < 8; ks++)
            s += d_part[(size_t)ks * (B_ * U_) + b * 512 + t + 128 * m];
        v[m] = s;
        S += s; Q += s * s;
    }
    S = red128s(S, sh); Q = red128s(Q, sh);
    float mean = S / 512.f;
    float rstd = rsqrtf(Q / 512.f - mean * mean + 1e-3f);
    float a0 = 0.f, a1 = 0.f, a2 = 0.f;
#pragma unroll
    for (int m = 0; m < 4; m++) {
        int i = t + 128 * m;
        float xn = (v[m] - mean) * rstd * g2g[i] + g2b[i];
        float e[9];
        kan_expand(xn, e);
        a0 += e[0] * k2base[i * 3 + 0];
        a1 += e[0] * k2base[i * 3 + 1];
        a2 += e[0] * k2base[i * 3 + 2];
#pragma unroll
        for (int j = 0; j < 8; j++) {
            const float* sp = k2spl + (size_t)(i * 8 + j) * 3;
            a0 += e[1 + j] * sp[0];
            a1 += e[1 + j] * sp[1];
            a2 += e[1 + j] * sp[2];
        }
    }
    a0 = red128s(a0, sh); a1 = red128s(a1, sh); a2 = red128s(a2, sh);
    if (t == 0) {
        float h2[3] = {a0, a1, a2};
        float y[3];
#pragma unroll
        for (int o = 0; o < 3; o++) {
            float g1 = gb[o], s1 = sb[o];
#pragma unroll
            for (int p = 0; p < 3; p++) { g1 += h2[p] * gw[p * 3 + o]; s1 += h2[p] * sw2[p * 3 + o]; }
            y[o] = d_skip[b * 3 + o] + g1 * sigm(s1);
        }
        float m = (y[0] + y[1] + y[2]) * (1.f / 3.f);
        float var = ((y[0] - m) * (y[0] - m) + (y[1] - m) * (y[1] - m) + (y[2] - m) * (y[2] - m)) * (1.f / 3.f);
        float rs = rsqrtf(var + 1e-3f);
        float yn[3], mx = -1e30f;
#pragma unroll
        for (int o = 0; o < 3; o++) { yn[o] = (y[o] - m) * rs * lg[o] + lb[o]; mx = fmaxf(mx, yn[o]); }
        float e0 = __expf(yn[0] - mx), e1 = __expf(yn[1] - mx), e2 = __expf(yn[2] - mx);
        float inv = 1.f / (e0 + e1 + e2);
        d_sigw[b * 3 + 0] = e0 * inv;
        d_sigw[b * 3 + 1] = e1 * inv;
        d_sigw[b * 3 + 2] = e2 * inv;
    }
}

DEV void subexpand_body(int bx, const float* lg, const float* lb, float* sh) {
    int t = threadIdx.x;
    int n = bx >> 10;
    float v = d_aggin[bx * 128 + t];
    float S = red128s(v, sh), Q = red128s(v * v, sh);
    float mean = S * (1.f / 128.f);
    float rstd = rsqrtf(Q * (1.f / 128.f) - mean * mean + 1e-3f);
    float xn = (v - mean) * rstd * lg[n * 128 + t] + lb[n * 128 + t];
    float e[9];
    kan_expand(xn, e);
    size_t base = (size_t)bx * 1152 + t * 9;
#pragma unroll
    for (int j = 0; j < 9; j++) d_subE[base + j] = e[j];
}

__global__ __launch_bounds__(128) void k_mid(
    const float* __restrict__ g2g, const float* __restrict__ g2b,
    const float* __restrict__ k2base, const float* __restrict__ k2spl,
    const float* __restrict__ gw, const float* __restrict__ gb,
    const float* __restrict__ sw2, const float* __restrict__ sb,
    const float* __restrict__ lg, const float* __restrict__ lb,
    const float* __restrict__ slg, const float* __restrict__ slb) {
    __shared__ float sh[128];
    int bid = blockIdx.x;
    if (bid < 1024) head_body(bid, g2g, g2b, k2base, k2spl, gw, gb, sw2, sb, lg, lb, sh);
    else            subexpand_body(bid - 1024, slg, slb, sh);
}

// ---------- K8: sub GEMM via tf32 MMA + epilogue ----------
__global__ __launch_bounds__(256) void k_subgemm(const float* __restrict__ ss,
                                                 const float* __restrict__ subk,
                                                 float* __restrict__ out_ss) {
    __shared__ uint32_t As4[128 * LDAZ];
    __shared__ uint32_t Bs4[32 * LDBZ];
    int tid = threadIdx.x, lane = tid & 31, wid = tid >> 5;
    int n = blockIdx.x, rowBase = blockIdx.y * 128;
    int warpRow = (wid & 3) * 32, warpCol = (wid >> 2) * 64;
    int g = lane >> 2, tg = lane & 3;
    int rsel = wid, n4 = lane * 4;
    int arow = tid >> 1, ahalf = tid & 1;
    const float* E = d_subE + (size_t)n * B_ * 1152;
    const float* W = d_subW + (size_t)n * 147456;

    float acc[2][8][4];
#pragma unroll
    for (int mi = 0; mi < 2; mi++)
#pragma unroll
        for (int ni = 0; ni < 8; ni++)
#pragma unroll
            for (int q = 0; q < 4; q++) acc[mi][ni][q] = 0.f;

    for (int kt = 0; kt < 1152; kt += 32) {
        const float* src = E + (size_t)(rowBase + arow) * 1152 + kt + ahalf * 16;
#pragma unroll
        for (int q = 0; q < 4; q++) {
            float4 v = *(const float4*)(src + q * 4);
            uint4 w;
            w.x = f2tf(v.x); w.y = f2tf(v.y); w.z = f2tf(v.z); w.w = f2tf(v.w);
            *(uint4*)&As4[arow * LDAZ + ahalf * 16 + q * 4] = w;
        }
#pragma unroll
        for (int i = 0; i < 4; i++) {
            int kl = i * 8 + rsel;
            float4 v = *(const float4*)(W + (size_t)(kt + kl) * 128 + n4);
            uint4 w;
            w.x = f2tf(v.x); w.y = f2tf(v.y); w.z = f2tf(v.z); w.w = f2tf(v.w);
            *(uint4*)&Bs4[kl * LDBZ + n4] = w;
        }
        __syncthreads();
#pragma unroll
        for (int ks2 = 0; ks2 < 4; ks2++) {
            int k0 = ks2 * 8;
            uint32_t aF[2][4];
#pragma unroll
            for (int mi = 0; mi < 2; mi++) {
                int r = warpRow + mi * 16;
                aF[mi][0] = As4[(r + g) * LDAZ + k0 + tg];
                aF[mi][1] = As4[(r + 8 + g) * LDAZ + k0 + tg];
                aF[mi][2] = As4[(r + g) * LDAZ + k0 + tg + 4];
                aF[mi][3] = As4[(r + 8 + g) * LDAZ + k0 + tg + 4];
            }
            uint32_t bF[8][2];
#pragma unroll
            for (int ni = 0; ni < 8; ni++) {
                int c = warpCol + ni * 8 + g;
                bF[ni][0] = Bs4[(k0 + tg) * LDBZ + c];
                bF[ni][1] = Bs4[(k0 + tg + 4) * LDBZ + c];
            }
#pragma unroll
            for (int mi = 0; mi < 2; mi++)
#pragma unroll
                for (int ni = 0; ni < 8; ni++)
                    mma_tf32(acc[mi][ni], aF[mi], bF[ni]);
        }
        __syncthreads();
    }
#pragma unroll
    for (int mi = 0; mi < 2; mi++)
#pragma unroll
        for (int ni = 0; ni < 8; ni++) {
            int col = warpCol + ni * 8 + tg * 2;
            float rkh0 = subk[n * 256 + col], rkh1 = subk[n * 256 + col + 1];
            float rkx0 = subk[n * 256 + 128 + col], rkx1 = subk[n * 256 + 128 + col + 1];
#pragma unroll
            for (int h = 0; h < 2; h++) {
                int row = rowBase + warpRow + mi * 16 + g + h * 8;
                float sgw = d_sigw[row * 3 + n];
                float v0 = acc[mi][ni][h * 2 + 0] * sgw;
                float v1 = acc[mi][ni][h * 2 + 1] * sgw;
                d_agg[row * 384 + n * 128 + col] = v0;
                d_agg[row * 384 + n * 128 + col + 1] = v1;
                size_t so = (size_t)n * 131072 + (size_t)row * 128 + col;
                out_ss[so]     = rkh0 * v0 + ss[so] * rkx0;
                out_ss[so + 1] = rkh1 * v1 + ss[so + 1] * rkx1;
            }
        }
}

// ---------- K9: x_o GEMM via tf32 MMA + final c, h ----------
__global__ __launch_bounds__(256) void k_final(const float* __restrict__ aw, const float* __restrict__ ab,
                                               const float* __restrict__ c0p, float* __restrict__ out) {
    __shared__ uint32_t As4[128 * LDAZ];
    __shared__ uint32_t Bs4[32 * LDBZ];
    int tid = threadIdx.x, lane = tid & 31, wid = tid >> 5;
    int colBase = blockIdx.x * 128, rowBase = blockIdx.y * 128;
    int warpRow = (wid & 3) * 32, warpCol = (wid >> 2) * 64;
    int g = lane >> 2, tg = lane & 3;
    int rsel = wid, n4 = lane * 4;
    int arow = tid >> 1, ahalf = tid & 1;

    float acc[2][8][4];
#pragma unroll
    for (int mi = 0; mi < 2; mi++)
#pragma unroll
        for (int ni = 0; ni < 8; ni++)
#pragma unroll
            for (int q = 0; q < 4; q++) acc[mi][ni][q] = 0.f;

    for (int kt = 0; kt < 384; kt += 32) {
        const float* src = d_agg + (size_t)(rowBase + arow) * 384 + kt + ahalf * 16;
#pragma unroll
        for (int q = 0; q < 4; q++) {
            float4 v = *(const float4*)(src + q * 4);
            uint4 w;
            w.x = f2tf(v.x); w.y = f2tf(v.y); w.z = f2tf(v.z); w.w = f2tf(v.w);
            *(uint4*)&As4[arow * LDAZ + ahalf * 16 + q * 4] = w;
        }
#pragma unroll
        for (int i = 0; i < 4; i++) {
            int kl = i * 8 + rsel;
            float4 v = *(const float4*)(aw + (size_t)(kt + kl) * 512 + colBase + n4);
            uint4 w;
            w.x = f2tf(v.x); w.y = f2tf(v.y); w.z = f2tf(v.z); w.w = f2tf(v.w);
            *(uint4*)&Bs4[kl * LDBZ + n4] = w;
        }
        __syncthreads();
#pragma unroll
        for (int ks2 = 0; ks2 < 4; ks2++) {
            int k0 = ks2 * 8;
            uint32_t aF[2][4];
#pragma unroll
            for (int mi = 0; mi < 2; mi++) {
                int r = warpRow + mi * 16;
                aF[mi][0] = As4[(r + g) * LDAZ + k0 + tg];
                aF[mi][1] = As4[(r + 8 + g) * LDAZ + k0 + tg];
                aF[mi][2] = As4[(r + g) * LDAZ + k0 + tg + 4];
                aF[mi][3] = As4[(r + 8 + g) * LDAZ + k0 + tg + 4];
            }
            uint32_t bF[8][2];
#pragma unroll
            for (int ni = 0; ni < 8; ni++) {
                int c = warpCol + ni * 8 + g;
                bF[ni][0] = Bs4[(k0 + tg) * LDBZ + c];
                bF[ni][1] = Bs4[(k0 + tg + 4) * LDBZ + c];
            }
#pragma unroll
            for (int mi = 0; mi < 2; mi++)
#pragma unroll
                for (int ni = 0; ni < 8; ni++)
                    mma_tf32(acc[mi][ni], aF[mi], bF[ni]);
        }
        __syncthreads();
    }
#pragma unroll
    for (int mi = 0; mi < 2; mi++)
#pragma unroll
        for (int ni = 0; ni < 8; ni++) {
            int col = colBase + warpCol + ni * 8 + tg * 2;
#pragma unroll
            for (int h = 0; h < 2; h++) {
                int row = rowBase + warpRow + mi * 16 + g + h * 8;
#pragma unroll
                for (int c = 0; c < 2; c++) {
                    int cc = col + c;
                    float xo = sigm(acc[mi][ni][h * 2 + c] + ab[cc]);
                    float zi = d_z[(size_t)row * 1536 + cc];
                    float zf = d_z[(size_t)row * 1536 + 512 + cc];
                    float zc = d_z[(size_t)row * 1536 + 1024 + cc];
                    float cv = zf * c0p[(size_t)row * 512 + cc] + zi * zc;
                    out[(size_t)row * 512 + cc] = xo * tanhf(cv);
                    out[B_ * U_ + (size_t)row * 512 + cc] = cv;
                }
            }
        }
}

// ---------- launch ----------
extern "C" void kernel_launch(void* const* d_in, const int* in_sizes, int n_in,
                              void* d_out, int out_size) {
    const float* inputs   = (const float*)d_in[0];
    const float* h0       = (const float*)d_in[1];
    const float* c0       = (const float*)d_in[2];
    const float* sub_st   = (const float*)d_in[3];
    const float* kern     = (const float*)d_in[4];
    const float* rkern    = (const float*)d_in[5];
    const float* bias     = (const float*)d_in[6];
    const float* sub_k    = (const float*)d_in[7];
    const float* sub_rki  = (const float*)d_in[8];
    const float* sub_rks  = (const float*)d_in[9];
    const float* agg_w    = (const float*)d_in[10];
    const float* agg_b    = (const float*)d_in[11];
    const float* sub_lng  = (const float*)d_in[12];
    const float* sub_lnb  = (const float*)d_in[13];
    const float* sub_bw   = (const float*)d_in[14];
    const float* sub_sw   = (const float*)d_in[15];
    const float* g_skw    = (const float*)d_in[16];
    const float* g_skb    = (const float*)d_in[17];
    const float* k1_lng   = (const float*)d_in[18];
    const float* k1_lnb   = (const float*)d_in[19];
    const float* k1_base  = (const float*)d_in[20];
    const float* k1_spl   = (const float*)d_in[21];
    const float* k2_lng   = (const float*)d_in[22];
    const float* k2_lnb   = (const float*)d_in[23];
    const float* k2_base  = (const float*)d_in[24];
    const float* k2_spl   = (const float*)d_in[25];
    const float* gw       = (const float*)d_in[26];
    const float* gb       = (const float*)d_in[27];
    const float* sw       = (const float*)d_in[28];
    const float* sb       = (const float*)d_in[29];
    const float* lg       = (const float*)d_in[30];
    const float* lb       = (const float*)d_in[31];
    float* out = (float*)d_out;

    static bool attr_set = false;
    if (!attr_set) {
        cudaFuncSetAttribute(k_mega, cudaFuncAttributeMaxDynamicSharedMemorySize, SM_MEGA);
        attr_set = true;
    }

    k_mega<<<3200, 256, SM_MEGA>>>(inputs, k1_lng, k1_lnb, k1_base, k1_spl,
                                   g_skw, g_skb, h0, kern, rkern, bias,
                                   sub_st, sub_rki, sub_rks, sub_bw, sub_sw);
    k_mid<<<4096, 128>>>(k2_lng, k2_lnb, k2_base, k2_spl, gw, gb, sw, sb, lg, lb,
                         sub_lng, sub_lnb);
    k_subgemm<<<dim3(3, 8), 256>>>(sub_st, sub_k, out + 2 * B_ * U_);
    k_final<<<dim3(4, 8), 256>>>(agg_w, agg_b, c0, out);
}